// round 12
// baseline (speedup 1.0000x reference)
#include <cuda_runtime.h>
#include <math.h>

#define BATCH 1024
#define DD 128
#define G3 384
#define TT 96
#define NSTEP 95
#define S_ODE 132
#define S_GRU 388

typedef unsigned long long u64;

__device__ __align__(256) float g_traj[(size_t)TT * BATCH * DD];
__device__ __align__(256) float g_gi[(size_t)TT * BATCH * G3];
__device__ __align__(256) float g_h1[(size_t)TT * BATCH * DD];
__device__ __align__(256) float g_h2[(size_t)BATCH * DD];

// ---- packed f32x2 + fast transcendental helpers ----
__device__ __forceinline__ u64 pack2(float lo, float hi) {
    u64 r; asm("mov.b64 %0,{%1,%2};" : "=l"(r) : "f"(lo), "f"(hi)); return r;
}
__device__ __forceinline__ u64 dup2(float v) { return pack2(v, v); }
__device__ __forceinline__ void unpk2(u64 v, float& lo, float& hi) {
    asm("mov.b64 {%0,%1},%2;" : "=f"(lo), "=f"(hi) : "l"(v));
}
__device__ __forceinline__ u64 ffma2(u64 a, u64 b, u64 c) {
    u64 d; asm("fma.rn.f32x2 %0,%1,%2,%3;" : "=l"(d) : "l"(a), "l"(b), "l"(c)); return d;
}
__device__ __forceinline__ u64 fadd2(u64 a, u64 b) {
    u64 d; asm("add.rn.f32x2 %0,%1,%2;" : "=l"(d) : "l"(a), "l"(b)); return d;
}
__device__ __forceinline__ float fex2(float x) { float r; asm("ex2.approx.f32 %0,%1;" : "=f"(r) : "f"(x)); return r; }
__device__ __forceinline__ float frcp(float x) { float r; asm("rcp.approx.f32 %0,%1;" : "=f"(r) : "f"(x)); return r; }
__device__ __forceinline__ float ftanh(float x) { return 1.0f - 2.0f * frcp(fex2(2.8853900817779268f * x) + 1.0f); }
__device__ __forceinline__ float fsigm(float x) { return frcp(1.0f + fex2(-1.4426950408889634f * x)); }
__device__ __forceinline__ u64 tanh2(u64 v) {
    float a, b; unpk2(v, a, b); return pack2(ftanh(a), ftanh(b));
}

// ---------------------------------------------------------------------------
// Phase 1: Dopri5 ODE, software-pipelined over 2 row-groups.
// 256 thr = 8 warps, 8 rows/CTA = 2 groups x 2 pairs, 128 CTAs.
// Segment s: matvec(group s&1, stage s>>1) + reduce/RK(group (s-1)&1, stage (s-1)>>1).
// Matvec role: warp q = k-slice [16q,16q+16), both pairs of the group.
// Reduce role: warp w owns (pair rp=w>>2, j=32*(w&3)+lane) of the red group.
// ---------------------------------------------------------------------------
__global__ void __launch_bounds__(256)
ode_kernel(const float* __restrict__ yl, const float* __restrict__ yh,
           const float* __restrict__ W, const float* __restrict__ bias)
{
    extern __shared__ float sm[];
    u64* pbuf = (u64*)(sm + S_ODE * DD);   // [g(2)][q(8)][pp(2)][j(128)] = 4096 u64 = 32KB
    u64* xs   = pbuf + 4096;               // [g(2)][pp(2)][k(128)] = 512 u64 = 4KB
    const int tid = threadIdx.x;
    for (int idx = tid; idx < DD * DD; idx += 256) {
        const int jj = idx >> 7, kk = idx & 127;
        sm[kk * S_ODE + jj] = W[idx];
    }
    const int lane = tid & 31, w = tid >> 5;
    const int q = w;                          // matvec k-slice
    const int rp = w >> 2, jq = w & 3;        // reduce role
    const int j = 32 * jq + lane;
    const int rowA0 = blockIdx.x * 8 + 2 * rp;          // group 0
    const int rowA1 = blockIdx.x * 8 + 4 + 2 * rp;      // group 1

    const u64 bv = dup2(bias[j]);
    const u64 dt2 = dup2(1.0f / 95.0f);

    u64 y[2], k1[2], k2[2], k3[2], k4[2], k5[2];
#pragma unroll
    for (int g = 0; g < 2; g++) {
        const int rA = g ? rowA1 : rowA0, rB = rA + 1;
        const float a0 = (j < 32) ? yl[rA * 32 + j] : yh[rA * 96 + j - 32];
        const float b0 = (j < 32) ? yl[rB * 32 + j] : yh[rB * 96 + j - 32];
        y[g] = pack2(a0, b0);
        g_traj[(size_t)rA * DD + j] = a0;
        g_traj[(size_t)rB * DD + j] = b0;
        xs[(g * 2 + rp) * 128 + j] = y[g];
    }
    __syncthreads();

    const int NSEG = NSTEP * 12;
    for (int s = 0; s <= NSEG; s++) {
        const int rg = (s - 1) & 1;
        // red phase 1: preload partials (latency overlapped with matvec)
        u64 pp8[8];
        if (s >= 1) {
            const u64* pb = pbuf + (size_t)(rg * 2048 + rp * 128 + j);
#pragma unroll
            for (int q8 = 0; q8 < 8; q8++) pp8[q8] = pb[(size_t)q8 * 256];
        }
        // matvec phase
        u64 acc[2][4];
        if (s < NSEG) {
            const int mg = s & 1;
            acc[0][0]=0; acc[0][1]=0; acc[0][2]=0; acc[0][3]=0;
            acc[1][0]=0; acc[1][1]=0; acc[1][2]=0; acc[1][3]=0;
            const u64* xb = xs + mg * 256;
#pragma unroll
            for (int kk = 0; kk < 16; kk++) {
                const int k = 16 * q + kk;
                const float4 wv = *(const float4*)(sm + k * S_ODE + 4 * lane);
                const u64 w0 = dup2(wv.x), w1 = dup2(wv.y), w2 = dup2(wv.z), w3 = dup2(wv.w);
                const u64 xA = xb[k], xB = xb[128 + k];
                acc[0][0]=ffma2(xA,w0,acc[0][0]); acc[0][1]=ffma2(xA,w1,acc[0][1]);
                acc[0][2]=ffma2(xA,w2,acc[0][2]); acc[0][3]=ffma2(xA,w3,acc[0][3]);
                acc[1][0]=ffma2(xB,w0,acc[1][0]); acc[1][1]=ffma2(xB,w1,acc[1][1]);
                acc[1][2]=ffma2(xB,w2,acc[1][2]); acc[1][3]=ffma2(xB,w3,acc[1][3]);
            }
        }
        // red phase 2: reduce + tanh + RK + store next x
        if (s >= 1) {
            u64 ssum = pp8[0];
#pragma unroll
            for (int q8 = 1; q8 < 8; q8++) ssum = fadd2(ssum, pp8[q8]);
            const u64 kv = tanh2(fadd2(ssum, bv));
            const int rgs = (s - 1) >> 1;
            const int step = rgs / 6;
            const int rstage = rgs - step * 6;
            u64 nx;
            if (rstage == 0) {
                k1[rg] = kv;
                nx = ffma2(dup2(0.2f / 95.0f), kv, y[rg]);
            } else if (rstage == 1) {
                k2[rg] = kv;
                u64 t = ffma2(dup2(0.225f), kv, ffma2(dup2(0.075f), k1[rg], (u64)0));
                nx = ffma2(dt2, t, y[rg]);
            } else if (rstage == 2) {
                k3[rg] = kv;
                u64 t = ffma2(dup2(0.9777777777777777f), k1[rg], (u64)0);
                t = ffma2(dup2(-3.7333333333333334f), k2[rg], t);
                t = ffma2(dup2(3.5555555555555554f), kv, t);
                nx = ffma2(dt2, t, y[rg]);
            } else if (rstage == 3) {
                k4[rg] = kv;
                u64 t = ffma2(dup2(2.9525906892141633f), k1[rg], (u64)0);
                t = ffma2(dup2(-11.595793324188385f), k2[rg], t);
                t = ffma2(dup2(9.822892851699436f), k3[rg], t);
                t = ffma2(dup2(-0.2908093278463649f), kv, t);
                nx = ffma2(dt2, t, y[rg]);
            } else if (rstage == 4) {
                k5[rg] = kv;
                u64 t = ffma2(dup2(2.8462752525252526f), k1[rg], (u64)0);
                t = ffma2(dup2(-10.757575757575758f), k2[rg], t);
                t = ffma2(dup2(8.906422717743473f), k3[rg], t);
                t = ffma2(dup2(0.2784090909090909f), k4[rg], t);
                t = ffma2(dup2(-0.2735313036020583f), kv, t);
                nx = ffma2(dt2, t, y[rg]);
            } else {
                u64 t = ffma2(dup2(0.09114583333333333f), k1[rg], (u64)0);
                t = ffma2(dup2(0.44923629829290207f), k3[rg], t);
                t = ffma2(dup2(0.6510416666666666f), k4[rg], t);
                t = ffma2(dup2(-0.322376179245283f), k5[rg], t);
                t = ffma2(dup2(0.13095238095238096f), kv, t);
                y[rg] = ffma2(dt2, t, y[rg]);
                nx = y[rg];
                float ca, cb;
                unpk2(y[rg], ca, cb);
                const int rA = rg ? rowA1 : rowA0;
                g_traj[((size_t)(step + 1) * BATCH + rA) * DD + j] = ca;
                g_traj[((size_t)(step + 1) * BATCH + rA + 1) * DD + j] = cb;
            }
            xs[(rg * 2 + rp) * 128 + j] = nx;
        }
        // matvec store partials
        if (s < NSEG) {
            const int mg = s & 1;
            u64* base = pbuf + (size_t)(mg * 2048 + q * 256) + 4 * lane;
            *(ulonglong2*)(base)           = make_ulonglong2(acc[0][0], acc[0][1]);
            *(ulonglong2*)(base + 2)       = make_ulonglong2(acc[0][2], acc[0][3]);
            *(ulonglong2*)(base + 128)     = make_ulonglong2(acc[1][0], acc[1][1]);
            *(ulonglong2*)(base + 130)     = make_ulonglong2(acc[1][2], acc[1][3]);
        }
        __syncthreads();
    }
}

// ---------------------------------------------------------------------------
// Phase 2/4: gi = X @ W_ih^T + b_ih (exact R6 version). 512 thr x 4 items.
// ---------------------------------------------------------------------------
__global__ void __launch_bounds__(512)
gi_kernel(const float* __restrict__ X, const float* __restrict__ Wih,
          const float* __restrict__ bih, float* __restrict__ gi)
{
    extern __shared__ float sm[];
    const int tid = threadIdx.x;
    for (int idx = tid; idx < G3 * DD; idx += 512) {
        const int j = idx >> 7, k = idx & 127;
        sm[k * S_GRU + j] = Wih[idx];
    }
    __syncthreads();

    const int lane = tid & 31, warp = tid >> 5;
    u64 bv[3][2];
#pragma unroll
    for (int g = 0; g < 3; g++) {
        bv[g][0] = pack2(bih[128 * g + 4 * lane], bih[128 * g + 4 * lane + 1]);
        bv[g][1] = pack2(bih[128 * g + 4 * lane + 2], bih[128 * g + 4 * lane + 3]);
    }
    const float* wb = sm + 4 * lane;

#pragma unroll 1
    for (int it = 0; it < 12; it++) {
        const int item = blockIdx.x * 768 + it * 64 + warp * 4;
        float a[4][4];
#pragma unroll
        for (int i = 0; i < 4; i++) {
            const float4 v = *(const float4*)(X + (size_t)(item + i) * DD + 4 * lane);
            a[i][0] = v.x; a[i][1] = v.y; a[i][2] = v.z; a[i][3] = v.w;
        }
        u64 acc[4][3][2];
#pragma unroll
        for (int i = 0; i < 4; i++)
#pragma unroll
            for (int g = 0; g < 3; g++) { acc[i][g][0] = bv[g][0]; acc[i][g][1] = bv[g][1]; }

#pragma unroll 2
        for (int kb = 0; kb < 32; kb++) {
#pragma unroll
            for (int mk = 0; mk < 4; mk++) {
                const int k = 4 * kb + mk;
                const ulonglong2 w0 = *(const ulonglong2*)(wb + k * S_GRU);
                const ulonglong2 w1 = *(const ulonglong2*)(wb + k * S_GRU + 128);
                const ulonglong2 w2 = *(const ulonglong2*)(wb + k * S_GRU + 256);
#pragma unroll
                for (int i = 0; i < 4; i++) {
                    const u64 xd = dup2(__shfl_sync(0xffffffffu, a[i][mk], kb));
                    acc[i][0][0] = ffma2(xd, w0.x, acc[i][0][0]);
                    acc[i][0][1] = ffma2(xd, w0.y, acc[i][0][1]);
                    acc[i][1][0] = ffma2(xd, w1.x, acc[i][1][0]);
                    acc[i][1][1] = ffma2(xd, w1.y, acc[i][1][1]);
                    acc[i][2][0] = ffma2(xd, w2.x, acc[i][2][0]);
                    acc[i][2][1] = ffma2(xd, w2.y, acc[i][2][1]);
                }
            }
        }
#pragma unroll
        for (int i = 0; i < 4; i++)
#pragma unroll
            for (int g = 0; g < 3; g++)
                *(ulonglong2*)(gi + (size_t)(item + i) * G3 + 128 * g + 4 * lane) =
                    make_ulonglong2(acc[i][g][0], acc[i][g][1]);
    }
}

// ---------------------------------------------------------------------------
// Phase 3/5: GRU scan (exact R6 version). 384 thr, 2 barriers/t.
// ---------------------------------------------------------------------------
__global__ void __launch_bounds__(384)
gru_kernel(const float* __restrict__ gi, const float* __restrict__ Whh,
           const float* __restrict__ bhh, float* __restrict__ otraj,
           float* __restrict__ olast)
{
    extern __shared__ float sm[];
    float* pbuf = sm + DD * S_GRU;   // 6144 floats: [(g*2+ks)*8 + row][128]
    float* xsf  = pbuf + 6144;       // 2048 floats: [row(8)][k] dup pairs
    u64* xsu = (u64*)xsf;
    const int tid = threadIdx.x;
    for (int idx = tid; idx < G3 * DD; idx += 384) {
        const int j = idx >> 7, k = idx & 127;
        sm[k * S_GRU + j] = Whh[idx];
    }
    for (int idx = tid; idx < 2048; idx += 384) xsf[idx] = 0.0f;
    __syncthreads();

    const int lane = tid & 31, wid = tid >> 5;
    const int g = wid >> 2, ks = (wid >> 1) & 1, rh = wid & 1;
    const float* wb = sm + g * 128 + 4 * lane;
    float* pme = pbuf + (size_t)((g * 2 + ks) * 8 + rh * 4) * 128 + 4 * lane;
    const int frow = wid;
    const bool fin = (wid < 8);
    const int grow = blockIdx.x * 8 + frow;

    float br[4], bz[4], bn[4];
    if (fin) {
        const float4 vr = *(const float4*)(bhh + 4 * lane);
        const float4 vz = *(const float4*)(bhh + 128 + 4 * lane);
        const float4 vn = *(const float4*)(bhh + 256 + 4 * lane);
        br[0]=vr.x; br[1]=vr.y; br[2]=vr.z; br[3]=vr.w;
        bz[0]=vz.x; bz[1]=vz.y; bz[2]=vz.z; bz[3]=vz.w;
        bn[0]=vn.x; bn[1]=vn.y; bn[2]=vn.z; bn[3]=vn.w;
    }
    float h[4] = {0.f, 0.f, 0.f, 0.f};

    for (int t = 0; t < TT; t++) {
        float4 gr_, gz_, gn_;
        if (fin) {
            const float* gp = gi + ((size_t)t * BATCH + grow) * G3 + 4 * lane;
            gr_ = *(const float4*)(gp);
            gz_ = *(const float4*)(gp + 128);
            gn_ = *(const float4*)(gp + 256);
        }
        u64 acc[4][2];
#pragma unroll
        for (int r = 0; r < 4; r++) { acc[r][0] = 0; acc[r][1] = 0; }
        const int kbase = 64 * ks;
#pragma unroll 8
        for (int kk = 0; kk < 64; kk += 2) {
            const int k = kbase + kk;
            const ulonglong2 x0 = *(const ulonglong2*)(xsu + (rh * 4 + 0) * 128 + k);
            const ulonglong2 x1 = *(const ulonglong2*)(xsu + (rh * 4 + 1) * 128 + k);
            const ulonglong2 x2 = *(const ulonglong2*)(xsu + (rh * 4 + 2) * 128 + k);
            const ulonglong2 x3 = *(const ulonglong2*)(xsu + (rh * 4 + 3) * 128 + k);
            const ulonglong2 wA = *(const ulonglong2*)(wb + k * S_GRU);
            const ulonglong2 wB = *(const ulonglong2*)(wb + (k + 1) * S_GRU);
            acc[0][0] = ffma2(x0.x, wA.x, acc[0][0]); acc[0][1] = ffma2(x0.x, wA.y, acc[0][1]);
            acc[1][0] = ffma2(x1.x, wA.x, acc[1][0]); acc[1][1] = ffma2(x1.x, wA.y, acc[1][1]);
            acc[2][0] = ffma2(x2.x, wA.x, acc[2][0]); acc[2][1] = ffma2(x2.x, wA.y, acc[2][1]);
            acc[3][0] = ffma2(x3.x, wA.x, acc[3][0]); acc[3][1] = ffma2(x3.x, wA.y, acc[3][1]);
            acc[0][0] = ffma2(x0.y, wB.x, acc[0][0]); acc[0][1] = ffma2(x0.y, wB.y, acc[0][1]);
            acc[1][0] = ffma2(x1.y, wB.x, acc[1][0]); acc[1][1] = ffma2(x1.y, wB.y, acc[1][1]);
            acc[2][0] = ffma2(x2.y, wB.x, acc[2][0]); acc[2][1] = ffma2(x2.y, wB.y, acc[2][1]);
            acc[3][0] = ffma2(x3.y, wB.x, acc[3][0]); acc[3][1] = ffma2(x3.y, wB.y, acc[3][1]);
        }
#pragma unroll
        for (int r = 0; r < 4; r++)
            *(ulonglong2*)(pme + r * 128) = make_ulonglong2(acc[r][0], acc[r][1]);
        __syncthreads();   // A: all partials visible

        if (fin) {
            const float* pb = pbuf + (size_t)frow * 128 + 4 * lane;
            const ulonglong2 pr0 = *(const ulonglong2*)(pb);
            const ulonglong2 pr1 = *(const ulonglong2*)(pb + 8 * 128);
            const ulonglong2 pz0 = *(const ulonglong2*)(pb + 16 * 128);
            const ulonglong2 pz1 = *(const ulonglong2*)(pb + 24 * 128);
            const ulonglong2 pn0 = *(const ulonglong2*)(pb + 32 * 128);
            const ulonglong2 pn1 = *(const ulonglong2*)(pb + 40 * 128);
            float ar[4], az[4], an[4];
            {
                const u64 s0 = fadd2(pr0.x, pr1.x), s1 = fadd2(pr0.y, pr1.y);
                unpk2(s0, ar[0], ar[1]); unpk2(s1, ar[2], ar[3]);
            }
            {
                const u64 s0 = fadd2(pz0.x, pz1.x), s1 = fadd2(pz0.y, pz1.y);
                unpk2(s0, az[0], az[1]); unpk2(s1, az[2], az[3]);
            }
            {
                const u64 s0 = fadd2(pn0.x, pn1.x), s1 = fadd2(pn0.y, pn1.y);
                unpk2(s0, an[0], an[1]); unpk2(s1, an[2], an[3]);
            }
            const float gvr[4] = {gr_.x, gr_.y, gr_.z, gr_.w};
            const float gvz[4] = {gz_.x, gz_.y, gz_.z, gz_.w};
            const float gvn[4] = {gn_.x, gn_.y, gn_.z, gn_.w};
#pragma unroll
            for (int m = 0; m < 4; m++) {
                const float rg = fsigm(gvr[m] + ar[m] + br[m]);
                const float zg = fsigm(gvz[m] + az[m] + bz[m]);
                const float ng = ftanh(gvn[m] + rg * (an[m] + bn[m]));
                h[m] = ng + zg * (h[m] - ng);
            }
            float* xme = xsf + (size_t)(frow * 128 + 4 * lane) * 2;
            *(float4*)(xme)     = make_float4(h[0], h[0], h[1], h[1]);
            *(float4*)(xme + 4) = make_float4(h[2], h[2], h[3], h[3]);
            if (otraj)
                *(float4*)(otraj + ((size_t)t * BATCH + grow) * DD + 4 * lane) =
                    make_float4(h[0], h[1], h[2], h[3]);
        }
        __syncthreads();   // B: new h visible
    }
    if (olast && fin)
        *(float4*)(olast + (size_t)grow * DD + 4 * lane) =
            make_float4(h[0], h[1], h[2], h[3]);
}

// ---------------------------------------------------------------------------
// Phase 6: FC head (unchanged).
// ---------------------------------------------------------------------------
__global__ void __launch_bounds__(256)
fc_kernel(const float* __restrict__ W1, const float* __restrict__ b1,
          const float* __restrict__ W2, const float* __restrict__ b2,
          float* __restrict__ out)
{
    extern __shared__ float sm[];
    float* hs = sm;
    float* hd = sm + 1024;
    float* wt = sm + 1536;
    const int tid = threadIdx.x;
    const int row0 = blockIdx.x * 8;

    for (int idx = tid; idx < 8 * DD; idx += 256) hs[idx] = g_h2[(size_t)row0 * DD + idx];
    for (int idx = tid; idx < 64 * DD; idx += 256) {
        const int j = idx >> 7, k = idx & 127;
        wt[k * 68 + j] = W1[idx];
    }
    __syncthreads();

#pragma unroll
    for (int i = 0; i < 2; i++) {
        const int p = tid + 256 * i, r = p >> 6, j = p & 63;
        float acc = b1[j];
#pragma unroll 8
        for (int k = 0; k < DD; k++) acc = fmaf(hs[r * DD + k], wt[k * 68 + j], acc);
        hd[r * 64 + j] = acc * normcdff(acc);
    }

    for (int c = 0; c < 12; c++) {
        __syncthreads();
        for (int idx = tid; idx < 256 * 64; idx += 256) {
            const int jj = idx >> 6, k = idx & 63;
            wt[k * 260 + jj] = W2[(size_t)(c * 256 + jj) * 64 + k];
        }
        __syncthreads();
        const int j = c * 256 + tid;
        float acc[8];
#pragma unroll
        for (int r = 0; r < 8; r++) acc[r] = b2[j];
#pragma unroll 8
        for (int k = 0; k < 64; k++) {
            const float w = wt[k * 260 + tid];
#pragma unroll
            for (int r = 0; r < 8; r++) acc[r] = fmaf(hd[r * 64 + k], w, acc[r]);
        }
#pragma unroll
        for (int r = 0; r < 8; r++) out[(size_t)(row0 + r) * 3072 + j] = acc[r];
    }
}

// ---------------------------------------------------------------------------
extern "C" void kernel_launch(void* const* d_in, const int* in_sizes, int n_in,
                              void* d_out, int out_size)
{
    (void)in_sizes; (void)n_in; (void)out_size;
    const float* yl    = (const float*)d_in[1];
    const float* yh    = (const float*)d_in[2];
    const float* W_ode = (const float*)d_in[3];
    const float* b_ode = (const float*)d_in[4];
    const float* W_ih0 = (const float*)d_in[5];
    const float* W_hh0 = (const float*)d_in[6];
    const float* b_ih0 = (const float*)d_in[7];
    const float* b_hh0 = (const float*)d_in[8];
    const float* W_ih1 = (const float*)d_in[9];
    const float* W_hh1 = (const float*)d_in[10];
    const float* b_ih1 = (const float*)d_in[11];
    const float* b_hh1 = (const float*)d_in[12];
    const float* W1    = (const float*)d_in[13];
    const float* b1    = (const float*)d_in[14];
    const float* W2    = (const float*)d_in[15];
    const float* b2    = (const float*)d_in[16];
    float* out = (float*)d_out;

    float *traj, *gibuf, *h1, *h2;
    cudaGetSymbolAddress((void**)&traj,  g_traj);
    cudaGetSymbolAddress((void**)&gibuf, g_gi);
    cudaGetSymbolAddress((void**)&h1,    g_h1);
    cudaGetSymbolAddress((void**)&h2,    g_h2);

    const int SM_ODE  = S_ODE * DD * 4 + 32768 + 4096;    // 104,448 B
    const int SM_GI   = S_GRU * DD * 4;                   // 198,656 B
    const int SM_GRU2 = (S_GRU * DD + 6144 + 2048) * 4;   // 231,424 B
    const int SM_FC   = (1536 + 64 * 260) * 4;            //  72,704 B
    cudaFuncSetAttribute(ode_kernel, cudaFuncAttributeMaxDynamicSharedMemorySize, SM_ODE);
    cudaFuncSetAttribute(gi_kernel,  cudaFuncAttributeMaxDynamicSharedMemorySize, SM_GI);
    cudaFuncSetAttribute(gru_kernel, cudaFuncAttributeMaxDynamicSharedMemorySize, SM_GRU2);
    cudaFuncSetAttribute(fc_kernel,  cudaFuncAttributeMaxDynamicSharedMemorySize, SM_FC);

    ode_kernel<<<128, 256, SM_ODE>>>(yl, yh, W_ode, b_ode);
    gi_kernel <<<128, 512, SM_GI>>>(traj, W_ih0, b_ih0, gibuf);
    gru_kernel<<<128, 384, SM_GRU2>>>(gibuf, W_hh0, b_hh0, h1, nullptr);
    gi_kernel <<<128, 512, SM_GI>>>(h1, W_ih1, b_ih1, gibuf);
    gru_kernel<<<128, 384, SM_GRU2>>>(gibuf, W_hh1, b_hh1, nullptr, h2);
    fc_kernel <<<128, 256, SM_FC>>>(W1, b1, W2, b2, out);
}

// round 13
// speedup vs baseline: 1.1549x; 1.1549x over previous
#include <cuda_runtime.h>
#include <math.h>

#define BATCH 1024
#define DD 128
#define G3 384
#define TT 96
#define NSTEP 95
#define S_ODE 132
#define S_GRU 388

typedef unsigned long long u64;

__device__ __align__(256) float g_traj[(size_t)TT * BATCH * DD];
__device__ __align__(256) float g_gi[(size_t)TT * BATCH * G3];
__device__ __align__(256) float g_h1[(size_t)TT * BATCH * DD];
__device__ __align__(256) float g_h2[(size_t)BATCH * DD];

// ---- packed f32x2 + fast transcendental helpers ----
__device__ __forceinline__ u64 pack2(float lo, float hi) {
    u64 r; asm("mov.b64 %0,{%1,%2};" : "=l"(r) : "f"(lo), "f"(hi)); return r;
}
__device__ __forceinline__ u64 dup2(float v) { return pack2(v, v); }
__device__ __forceinline__ void unpk2(u64 v, float& lo, float& hi) {
    asm("mov.b64 {%0,%1},%2;" : "=f"(lo), "=f"(hi) : "l"(v));
}
__device__ __forceinline__ u64 ffma2(u64 a, u64 b, u64 c) {
    u64 d; asm("fma.rn.f32x2 %0,%1,%2,%3;" : "=l"(d) : "l"(a), "l"(b), "l"(c)); return d;
}
__device__ __forceinline__ u64 fadd2(u64 a, u64 b) {
    u64 d; asm("add.rn.f32x2 %0,%1,%2;" : "=l"(d) : "l"(a), "l"(b)); return d;
}
__device__ __forceinline__ float fex2(float x) { float r; asm("ex2.approx.f32 %0,%1;" : "=f"(r) : "f"(x)); return r; }
__device__ __forceinline__ float frcp(float x) { float r; asm("rcp.approx.f32 %0,%1;" : "=f"(r) : "f"(x)); return r; }
__device__ __forceinline__ float ftanh(float x) { return 1.0f - 2.0f * frcp(fex2(2.8853900817779268f * x) + 1.0f); }
__device__ __forceinline__ float fsigm(float x) { return frcp(1.0f + fex2(-1.4426950408889634f * x)); }
__device__ __forceinline__ u64 tanh2(u64 v) {
    float a, b; unpk2(v, a, b); return pack2(ftanh(a), ftanh(b));
}

// ---------------------------------------------------------------------------
// Phase 1: Dopri5 ODE (R7 design + paired xs broadcasts). 256 thr = 8 warps,
// 8 rows = 4 row-pairs (f32x2). Matvec role: warp q = k-slice [16q,16q+16),
// all 4 pairs. Reduce/RK role: warp (p = w>>1 pair, jh = w&1 j-half).
// ---------------------------------------------------------------------------
__global__ void __launch_bounds__(256)
ode_kernel(const float* __restrict__ yl, const float* __restrict__ yh,
           const float* __restrict__ W, const float* __restrict__ bias)
{
    extern __shared__ float sm[];
    u64* pbuf = (u64*)(sm + S_ODE * DD);   // [q(8)][p(4)][j(128)] u64 = 32KB
    u64* xs   = pbuf + 4096;               // [p(4)][k(128)] u64 = 4KB
    const int tid = threadIdx.x;
    for (int idx = tid; idx < DD * DD; idx += 256) {
        const int j = idx >> 7, k = idx & 127;
        sm[k * S_ODE + j] = W[idx];
    }
    const int lane = tid & 31, w = tid >> 5;
    const int q = w;                       // matvec k-slice
    const int p = w >> 1, jh = w & 1;      // finalize role
    const int j0 = 64 * jh + 2 * lane;
    const int rowA = blockIdx.x * 8 + 2 * p, rowB = rowA + 1;

    const u64 bv0 = dup2(bias[j0]), bv1 = dup2(bias[j0 + 1]);

    float a0 = (j0 < 32) ? yl[rowA * 32 + j0] : yh[rowA * 96 + j0 - 32];
    float b0 = (j0 < 32) ? yl[rowB * 32 + j0] : yh[rowB * 96 + j0 - 32];
    float a1 = (j0 + 1 < 32) ? yl[rowA * 32 + j0 + 1] : yh[rowA * 96 + j0 + 1 - 32];
    float b1 = (j0 + 1 < 32) ? yl[rowB * 32 + j0 + 1] : yh[rowB * 96 + j0 + 1 - 32];
    u64 y0 = pack2(a0, b0), y1 = pack2(a1, b1);
    *(float2*)(g_traj + (size_t)rowA * DD + j0) = make_float2(a0, a1);
    *(float2*)(g_traj + (size_t)rowB * DD + j0) = make_float2(b0, b1);
    *(ulonglong2*)(xs + p * 128 + j0) = make_ulonglong2(y0, y1);
    __syncthreads();

    const u64 dt2 = dup2(1.0f / 95.0f);
    u64 k1[2], k2[2], k3[2], k4[2], k5[2], k6[2], ar[2];

#define ODE_EVAL(KOUT) do { \
    u64 acc[4][4]; \
    _Pragma("unroll") \
    for (int pp = 0; pp < 4; pp++) { acc[pp][0]=0; acc[pp][1]=0; acc[pp][2]=0; acc[pp][3]=0; } \
    _Pragma("unroll") \
    for (int kk = 0; kk < 16; kk += 2) { \
        const int k = 16 * q + kk; \
        const float4 wvA = *(const float4*)(sm + k * S_ODE + 4 * lane); \
        const float4 wvB = *(const float4*)(sm + (k + 1) * S_ODE + 4 * lane); \
        const ulonglong2 xp0 = *(const ulonglong2*)(xs + k); \
        const ulonglong2 xp1 = *(const ulonglong2*)(xs + 128 + k); \
        const ulonglong2 xp2 = *(const ulonglong2*)(xs + 256 + k); \
        const ulonglong2 xp3 = *(const ulonglong2*)(xs + 384 + k); \
        { \
            const u64 w0 = dup2(wvA.x), w1 = dup2(wvA.y), w2 = dup2(wvA.z), w3 = dup2(wvA.w); \
            acc[0][0]=ffma2(xp0.x,w0,acc[0][0]); acc[0][1]=ffma2(xp0.x,w1,acc[0][1]); \
            acc[0][2]=ffma2(xp0.x,w2,acc[0][2]); acc[0][3]=ffma2(xp0.x,w3,acc[0][3]); \
            acc[1][0]=ffma2(xp1.x,w0,acc[1][0]); acc[1][1]=ffma2(xp1.x,w1,acc[1][1]); \
            acc[1][2]=ffma2(xp1.x,w2,acc[1][2]); acc[1][3]=ffma2(xp1.x,w3,acc[1][3]); \
            acc[2][0]=ffma2(xp2.x,w0,acc[2][0]); acc[2][1]=ffma2(xp2.x,w1,acc[2][1]); \
            acc[2][2]=ffma2(xp2.x,w2,acc[2][2]); acc[2][3]=ffma2(xp2.x,w3,acc[2][3]); \
            acc[3][0]=ffma2(xp3.x,w0,acc[3][0]); acc[3][1]=ffma2(xp3.x,w1,acc[3][1]); \
            acc[3][2]=ffma2(xp3.x,w2,acc[3][2]); acc[3][3]=ffma2(xp3.x,w3,acc[3][3]); \
        } \
        { \
            const u64 w0 = dup2(wvB.x), w1 = dup2(wvB.y), w2 = dup2(wvB.z), w3 = dup2(wvB.w); \
            acc[0][0]=ffma2(xp0.y,w0,acc[0][0]); acc[0][1]=ffma2(xp0.y,w1,acc[0][1]); \
            acc[0][2]=ffma2(xp0.y,w2,acc[0][2]); acc[0][3]=ffma2(xp0.y,w3,acc[0][3]); \
            acc[1][0]=ffma2(xp1.y,w0,acc[1][0]); acc[1][1]=ffma2(xp1.y,w1,acc[1][1]); \
            acc[1][2]=ffma2(xp1.y,w2,acc[1][2]); acc[1][3]=ffma2(xp1.y,w3,acc[1][3]); \
            acc[2][0]=ffma2(xp2.y,w0,acc[2][0]); acc[2][1]=ffma2(xp2.y,w1,acc[2][1]); \
            acc[2][2]=ffma2(xp2.y,w2,acc[2][2]); acc[2][3]=ffma2(xp2.y,w3,acc[2][3]); \
            acc[3][0]=ffma2(xp3.y,w0,acc[3][0]); acc[3][1]=ffma2(xp3.y,w1,acc[3][1]); \
            acc[3][2]=ffma2(xp3.y,w2,acc[3][2]); acc[3][3]=ffma2(xp3.y,w3,acc[3][3]); \
        } \
    } \
    _Pragma("unroll") \
    for (int pp = 0; pp < 4; pp++) { \
        u64* base = pbuf + (size_t)(q * 4 + pp) * 128 + 4 * lane; \
        *(ulonglong2*)(base)     = make_ulonglong2(acc[pp][0], acc[pp][1]); \
        *(ulonglong2*)(base + 2) = make_ulonglong2(acc[pp][2], acc[pp][3]); \
    } \
    __syncthreads(); \
    u64 s0 = bv0, s1 = bv1; \
    _Pragma("unroll") \
    for (int qq = 0; qq < 8; qq++) { \
        const ulonglong2 v = *(const ulonglong2*)(pbuf + (size_t)(qq * 4 + p) * 128 + j0); \
        s0 = fadd2(s0, v.x); s1 = fadd2(s1, v.y); \
    } \
    KOUT[0] = tanh2(s0); KOUT[1] = tanh2(s1); \
} while (0)

#define ODE_PUSH() do { \
    *(ulonglong2*)(xs + p * 128 + j0) = make_ulonglong2(ar[0], ar[1]); \
    __syncthreads(); } while (0)

    for (int st = 0; st < NSTEP; st++) {
        ODE_EVAL(k1);
        {
            const u64 c = dup2(0.2f / 95.0f);
            ar[0] = ffma2(c, k1[0], y0); ar[1] = ffma2(c, k1[1], y1);
        }
        ODE_PUSH();

        ODE_EVAL(k2);
#pragma unroll
        for (int m = 0; m < 2; m++) {
            u64 s = ffma2(dup2(0.225f), k2[m], ffma2(dup2(0.075f), k1[m], (u64)0));
            ar[m] = ffma2(dt2, s, m ? y1 : y0);
        }
        ODE_PUSH();

        ODE_EVAL(k3);
#pragma unroll
        for (int m = 0; m < 2; m++) {
            u64 s = ffma2(dup2(0.9777777777777777f), k1[m], (u64)0);
            s = ffma2(dup2(-3.7333333333333334f), k2[m], s);
            s = ffma2(dup2(3.5555555555555554f), k3[m], s);
            ar[m] = ffma2(dt2, s, m ? y1 : y0);
        }
        ODE_PUSH();

        ODE_EVAL(k4);
#pragma unroll
        for (int m = 0; m < 2; m++) {
            u64 s = ffma2(dup2(2.9525906892141633f), k1[m], (u64)0);
            s = ffma2(dup2(-11.595793324188385f), k2[m], s);
            s = ffma2(dup2(9.822892851699436f), k3[m], s);
            s = ffma2(dup2(-0.2908093278463649f), k4[m], s);
            ar[m] = ffma2(dt2, s, m ? y1 : y0);
        }
        ODE_PUSH();

        ODE_EVAL(k5);
#pragma unroll
        for (int m = 0; m < 2; m++) {
            u64 s = ffma2(dup2(2.8462752525252526f), k1[m], (u64)0);
            s = ffma2(dup2(-10.757575757575758f), k2[m], s);
            s = ffma2(dup2(8.906422717743473f), k3[m], s);
            s = ffma2(dup2(0.2784090909090909f), k4[m], s);
            s = ffma2(dup2(-0.2735313036020583f), k5[m], s);
            ar[m] = ffma2(dt2, s, m ? y1 : y0);
        }
        ODE_PUSH();

        ODE_EVAL(k6);
#pragma unroll
        for (int m = 0; m < 2; m++) {
            u64 s = ffma2(dup2(0.09114583333333333f), k1[m], (u64)0);
            s = ffma2(dup2(0.44923629829290207f), k3[m], s);
            s = ffma2(dup2(0.6510416666666666f), k4[m], s);
            s = ffma2(dup2(-0.322376179245283f), k5[m], s);
            s = ffma2(dup2(0.13095238095238096f), k6[m], s);
            if (m == 0) y0 = ffma2(dt2, s, y0); else y1 = ffma2(dt2, s, y1);
        }
        {
            float c0, d0, c1, d1;
            unpk2(y0, c0, d0); unpk2(y1, c1, d1);
            *(float2*)(g_traj + ((size_t)(st + 1) * BATCH + rowA) * DD + j0) = make_float2(c0, c1);
            *(float2*)(g_traj + ((size_t)(st + 1) * BATCH + rowB) * DD + j0) = make_float2(d0, d1);
        }
        *(ulonglong2*)(xs + p * 128 + j0) = make_ulonglong2(y0, y1);
        __syncthreads();
    }
#undef ODE_EVAL
#undef ODE_PUSH
}

// ---------------------------------------------------------------------------
// Phase 2/4: gi = X @ W_ih^T + b_ih (exact R6 version). 512 thr x 4 items.
// ---------------------------------------------------------------------------
__global__ void __launch_bounds__(512)
gi_kernel(const float* __restrict__ X, const float* __restrict__ Wih,
          const float* __restrict__ bih, float* __restrict__ gi)
{
    extern __shared__ float sm[];
    const int tid = threadIdx.x;
    for (int idx = tid; idx < G3 * DD; idx += 512) {
        const int j = idx >> 7, k = idx & 127;
        sm[k * S_GRU + j] = Wih[idx];
    }
    __syncthreads();

    const int lane = tid & 31, warp = tid >> 5;
    u64 bv[3][2];
#pragma unroll
    for (int g = 0; g < 3; g++) {
        bv[g][0] = pack2(bih[128 * g + 4 * lane], bih[128 * g + 4 * lane + 1]);
        bv[g][1] = pack2(bih[128 * g + 4 * lane + 2], bih[128 * g + 4 * lane + 3]);
    }
    const float* wb = sm + 4 * lane;

#pragma unroll 1
    for (int it = 0; it < 12; it++) {
        const int item = blockIdx.x * 768 + it * 64 + warp * 4;
        float a[4][4];
#pragma unroll
        for (int i = 0; i < 4; i++) {
            const float4 v = *(const float4*)(X + (size_t)(item + i) * DD + 4 * lane);
            a[i][0] = v.x; a[i][1] = v.y; a[i][2] = v.z; a[i][3] = v.w;
        }
        u64 acc[4][3][2];
#pragma unroll
        for (int i = 0; i < 4; i++)
#pragma unroll
            for (int g = 0; g < 3; g++) { acc[i][g][0] = bv[g][0]; acc[i][g][1] = bv[g][1]; }

#pragma unroll 2
        for (int kb = 0; kb < 32; kb++) {
#pragma unroll
            for (int mk = 0; mk < 4; mk++) {
                const int k = 4 * kb + mk;
                const ulonglong2 w0 = *(const ulonglong2*)(wb + k * S_GRU);
                const ulonglong2 w1 = *(const ulonglong2*)(wb + k * S_GRU + 128);
                const ulonglong2 w2 = *(const ulonglong2*)(wb + k * S_GRU + 256);
#pragma unroll
                for (int i = 0; i < 4; i++) {
                    const u64 xd = dup2(__shfl_sync(0xffffffffu, a[i][mk], kb));
                    acc[i][0][0] = ffma2(xd, w0.x, acc[i][0][0]);
                    acc[i][0][1] = ffma2(xd, w0.y, acc[i][0][1]);
                    acc[i][1][0] = ffma2(xd, w1.x, acc[i][1][0]);
                    acc[i][1][1] = ffma2(xd, w1.y, acc[i][1][1]);
                    acc[i][2][0] = ffma2(xd, w2.x, acc[i][2][0]);
                    acc[i][2][1] = ffma2(xd, w2.y, acc[i][2][1]);
                }
            }
        }
#pragma unroll
        for (int i = 0; i < 4; i++)
#pragma unroll
            for (int g = 0; g < 3; g++)
                *(ulonglong2*)(gi + (size_t)(item + i) * G3 + 128 * g + 4 * lane) =
                    make_ulonglong2(acc[i][g][0], acc[i][g][1]);
    }
}

// ---------------------------------------------------------------------------
// Phase 3/5: GRU scan (exact R6 version). 384 thr, 2 barriers/t.
// ---------------------------------------------------------------------------
__global__ void __launch_bounds__(384)
gru_kernel(const float* __restrict__ gi, const float* __restrict__ Whh,
           const float* __restrict__ bhh, float* __restrict__ otraj,
           float* __restrict__ olast)
{
    extern __shared__ float sm[];
    float* pbuf = sm + DD * S_GRU;   // 6144 floats: [(g*2+ks)*8 + row][128]
    float* xsf  = pbuf + 6144;       // 2048 floats: [row(8)][k] dup pairs
    u64* xsu = (u64*)xsf;
    const int tid = threadIdx.x;
    for (int idx = tid; idx < G3 * DD; idx += 384) {
        const int j = idx >> 7, k = idx & 127;
        sm[k * S_GRU + j] = Whh[idx];
    }
    for (int idx = tid; idx < 2048; idx += 384) xsf[idx] = 0.0f;
    __syncthreads();

    const int lane = tid & 31, wid = tid >> 5;
    const int g = wid >> 2, ks = (wid >> 1) & 1, rh = wid & 1;
    const float* wb = sm + g * 128 + 4 * lane;
    float* pme = pbuf + (size_t)((g * 2 + ks) * 8 + rh * 4) * 128 + 4 * lane;
    const int frow = wid;
    const bool fin = (wid < 8);
    const int grow = blockIdx.x * 8 + frow;

    float br[4], bz[4], bn[4];
    if (fin) {
        const float4 vr = *(const float4*)(bhh + 4 * lane);
        const float4 vz = *(const float4*)(bhh + 128 + 4 * lane);
        const float4 vn = *(const float4*)(bhh + 256 + 4 * lane);
        br[0]=vr.x; br[1]=vr.y; br[2]=vr.z; br[3]=vr.w;
        bz[0]=vz.x; bz[1]=vz.y; bz[2]=vz.z; bz[3]=vz.w;
        bn[0]=vn.x; bn[1]=vn.y; bn[2]=vn.z; bn[3]=vn.w;
    }
    float h[4] = {0.f, 0.f, 0.f, 0.f};

    for (int t = 0; t < TT; t++) {
        float4 gr_, gz_, gn_;
        if (fin) {
            const float* gp = gi + ((size_t)t * BATCH + grow) * G3 + 4 * lane;
            gr_ = *(const float4*)(gp);
            gz_ = *(const float4*)(gp + 128);
            gn_ = *(const float4*)(gp + 256);
        }
        u64 acc[4][2];
#pragma unroll
        for (int r = 0; r < 4; r++) { acc[r][0] = 0; acc[r][1] = 0; }
        const int kbase = 64 * ks;
#pragma unroll 8
        for (int kk = 0; kk < 64; kk += 2) {
            const int k = kbase + kk;
            const ulonglong2 x0 = *(const ulonglong2*)(xsu + (rh * 4 + 0) * 128 + k);
            const ulonglong2 x1 = *(const ulonglong2*)(xsu + (rh * 4 + 1) * 128 + k);
            const ulonglong2 x2 = *(const ulonglong2*)(xsu + (rh * 4 + 2) * 128 + k);
            const ulonglong2 x3 = *(const ulonglong2*)(xsu + (rh * 4 + 3) * 128 + k);
            const ulonglong2 wA = *(const ulonglong2*)(wb + k * S_GRU);
            const ulonglong2 wB = *(const ulonglong2*)(wb + (k + 1) * S_GRU);
            acc[0][0] = ffma2(x0.x, wA.x, acc[0][0]); acc[0][1] = ffma2(x0.x, wA.y, acc[0][1]);
            acc[1][0] = ffma2(x1.x, wA.x, acc[1][0]); acc[1][1] = ffma2(x1.x, wA.y, acc[1][1]);
            acc[2][0] = ffma2(x2.x, wA.x, acc[2][0]); acc[2][1] = ffma2(x2.x, wA.y, acc[2][1]);
            acc[3][0] = ffma2(x3.x, wA.x, acc[3][0]); acc[3][1] = ffma2(x3.x, wA.y, acc[3][1]);
            acc[0][0] = ffma2(x0.y, wB.x, acc[0][0]); acc[0][1] = ffma2(x0.y, wB.y, acc[0][1]);
            acc[1][0] = ffma2(x1.y, wB.x, acc[1][0]); acc[1][1] = ffma2(x1.y, wB.y, acc[1][1]);
            acc[2][0] = ffma2(x2.y, wB.x, acc[2][0]); acc[2][1] = ffma2(x2.y, wB.y, acc[2][1]);
            acc[3][0] = ffma2(x3.y, wB.x, acc[3][0]); acc[3][1] = ffma2(x3.y, wB.y, acc[3][1]);
        }
#pragma unroll
        for (int r = 0; r < 4; r++)
            *(ulonglong2*)(pme + r * 128) = make_ulonglong2(acc[r][0], acc[r][1]);
        __syncthreads();   // A: all partials visible

        if (fin) {
            const float* pb = pbuf + (size_t)frow * 128 + 4 * lane;
            const ulonglong2 pr0 = *(const ulonglong2*)(pb);
            const ulonglong2 pr1 = *(const ulonglong2*)(pb + 8 * 128);
            const ulonglong2 pz0 = *(const ulonglong2*)(pb + 16 * 128);
            const ulonglong2 pz1 = *(const ulonglong2*)(pb + 24 * 128);
            const ulonglong2 pn0 = *(const ulonglong2*)(pb + 32 * 128);
            const ulonglong2 pn1 = *(const ulonglong2*)(pb + 40 * 128);
            float ar[4], az[4], an[4];
            {
                const u64 s0 = fadd2(pr0.x, pr1.x), s1 = fadd2(pr0.y, pr1.y);
                unpk2(s0, ar[0], ar[1]); unpk2(s1, ar[2], ar[3]);
            }
            {
                const u64 s0 = fadd2(pz0.x, pz1.x), s1 = fadd2(pz0.y, pz1.y);
                unpk2(s0, az[0], az[1]); unpk2(s1, az[2], az[3]);
            }
            {
                const u64 s0 = fadd2(pn0.x, pn1.x), s1 = fadd2(pn0.y, pn1.y);
                unpk2(s0, an[0], an[1]); unpk2(s1, an[2], an[3]);
            }
            const float gvr[4] = {gr_.x, gr_.y, gr_.z, gr_.w};
            const float gvz[4] = {gz_.x, gz_.y, gz_.z, gz_.w};
            const float gvn[4] = {gn_.x, gn_.y, gn_.z, gn_.w};
#pragma unroll
            for (int m = 0; m < 4; m++) {
                const float rg = fsigm(gvr[m] + ar[m] + br[m]);
                const float zg = fsigm(gvz[m] + az[m] + bz[m]);
                const float ng = ftanh(gvn[m] + rg * (an[m] + bn[m]));
                h[m] = ng + zg * (h[m] - ng);
            }
            float* xme = xsf + (size_t)(frow * 128 + 4 * lane) * 2;
            *(float4*)(xme)     = make_float4(h[0], h[0], h[1], h[1]);
            *(float4*)(xme + 4) = make_float4(h[2], h[2], h[3], h[3]);
            if (otraj)
                *(float4*)(otraj + ((size_t)t * BATCH + grow) * DD + 4 * lane) =
                    make_float4(h[0], h[1], h[2], h[3]);
        }
        __syncthreads();   // B: new h visible
    }
    if (olast && fin)
        *(float4*)(olast + (size_t)grow * DD + 4 * lane) =
            make_float4(h[0], h[1], h[2], h[3]);
}

// ---------------------------------------------------------------------------
// Phase 6: FC head (unchanged).
// ---------------------------------------------------------------------------
__global__ void __launch_bounds__(256)
fc_kernel(const float* __restrict__ W1, const float* __restrict__ b1,
          const float* __restrict__ W2, const float* __restrict__ b2,
          float* __restrict__ out)
{
    extern __shared__ float sm[];
    float* hs = sm;
    float* hd = sm + 1024;
    float* wt = sm + 1536;
    const int tid = threadIdx.x;
    const int row0 = blockIdx.x * 8;

    for (int idx = tid; idx < 8 * DD; idx += 256) hs[idx] = g_h2[(size_t)row0 * DD + idx];
    for (int idx = tid; idx < 64 * DD; idx += 256) {
        const int j = idx >> 7, k = idx & 127;
        wt[k * 68 + j] = W1[idx];
    }
    __syncthreads();

#pragma unroll
    for (int i = 0; i < 2; i++) {
        const int p = tid + 256 * i, r = p >> 6, j = p & 63;
        float acc = b1[j];
#pragma unroll 8
        for (int k = 0; k < DD; k++) acc = fmaf(hs[r * DD + k], wt[k * 68 + j], acc);
        hd[r * 64 + j] = acc * normcdff(acc);
    }

    for (int c = 0; c < 12; c++) {
        __syncthreads();
        for (int idx = tid; idx < 256 * 64; idx += 256) {
            const int jj = idx >> 6, k = idx & 63;
            wt[k * 260 + jj] = W2[(size_t)(c * 256 + jj) * 64 + k];
        }
        __syncthreads();
        const int j = c * 256 + tid;
        float acc[8];
#pragma unroll
        for (int r = 0; r < 8; r++) acc[r] = b2[j];
#pragma unroll 8
        for (int k = 0; k < 64; k++) {
            const float w = wt[k * 260 + tid];
#pragma unroll
            for (int r = 0; r < 8; r++) acc[r] = fmaf(hd[r * 64 + k], w, acc[r]);
        }
#pragma unroll
        for (int r = 0; r < 8; r++) out[(size_t)(row0 + r) * 3072 + j] = acc[r];
    }
}

// ---------------------------------------------------------------------------
extern "C" void kernel_launch(void* const* d_in, const int* in_sizes, int n_in,
                              void* d_out, int out_size)
{
    (void)in_sizes; (void)n_in; (void)out_size;
    const float* yl    = (const float*)d_in[1];
    const float* yh    = (const float*)d_in[2];
    const float* W_ode = (const float*)d_in[3];
    const float* b_ode = (const float*)d_in[4];
    const float* W_ih0 = (const float*)d_in[5];
    const float* W_hh0 = (const float*)d_in[6];
    const float* b_ih0 = (const float*)d_in[7];
    const float* b_hh0 = (const float*)d_in[8];
    const float* W_ih1 = (const float*)d_in[9];
    const float* W_hh1 = (const float*)d_in[10];
    const float* b_ih1 = (const float*)d_in[11];
    const float* b_hh1 = (const float*)d_in[12];
    const float* W1    = (const float*)d_in[13];
    const float* b1    = (const float*)d_in[14];
    const float* W2    = (const float*)d_in[15];
    const float* b2    = (const float*)d_in[16];
    float* out = (float*)d_out;

    float *traj, *gibuf, *h1, *h2;
    cudaGetSymbolAddress((void**)&traj,  g_traj);
    cudaGetSymbolAddress((void**)&gibuf, g_gi);
    cudaGetSymbolAddress((void**)&h1,    g_h1);
    cudaGetSymbolAddress((void**)&h2,    g_h2);

    const int SM_ODE  = S_ODE * DD * 4 + 32768 + 4096;    // 104,448 B
    const int SM_GI   = S_GRU * DD * 4;                   // 198,656 B
    const int SM_GRU2 = (S_GRU * DD + 6144 + 2048) * 4;   // 231,424 B
    const int SM_FC   = (1536 + 64 * 260) * 4;            //  72,704 B
    cudaFuncSetAttribute(ode_kernel, cudaFuncAttributeMaxDynamicSharedMemorySize, SM_ODE);
    cudaFuncSetAttribute(gi_kernel,  cudaFuncAttributeMaxDynamicSharedMemorySize, SM_GI);
    cudaFuncSetAttribute(gru_kernel, cudaFuncAttributeMaxDynamicSharedMemorySize, SM_GRU2);
    cudaFuncSetAttribute(fc_kernel,  cudaFuncAttributeMaxDynamicSharedMemorySize, SM_FC);

    ode_kernel<<<128, 256, SM_ODE>>>(yl, yh, W_ode, b_ode);
    gi_kernel <<<128, 512, SM_GI>>>(traj, W_ih0, b_ih0, gibuf);
    gru_kernel<<<128, 384, SM_GRU2>>>(gibuf, W_hh0, b_hh0, h1, nullptr);
    gi_kernel <<<128, 512, SM_GI>>>(h1, W_ih1, b_ih1, gibuf);
    gru_kernel<<<128, 384, SM_GRU2>>>(gibuf, W_hh1, b_hh1, nullptr, h2);
    fc_kernel <<<128, 256, SM_FC>>>(W1, b1, W2, b2, out);
}

// round 14
// speedup vs baseline: 1.2506x; 1.0828x over previous
#include <cuda_runtime.h>
#include <math.h>

#define BATCH 1024
#define DD 128
#define G3 384
#define TT 96
#define NSTEP 95
#define S_ODE 132
#define S_GRU 388

typedef unsigned long long u64;

__device__ __align__(256) float g_traj[(size_t)TT * BATCH * DD];
__device__ __align__(256) float g_gi[(size_t)TT * BATCH * G3];
__device__ __align__(256) float g_h1[(size_t)TT * BATCH * DD];
__device__ __align__(256) float g_h2[(size_t)BATCH * DD];

// ---- packed f32x2 + fast transcendental helpers ----
__device__ __forceinline__ u64 pack2(float lo, float hi) {
    u64 r; asm("mov.b64 %0,{%1,%2};" : "=l"(r) : "f"(lo), "f"(hi)); return r;
}
__device__ __forceinline__ u64 dup2(float v) { return pack2(v, v); }
__device__ __forceinline__ void unpk2(u64 v, float& lo, float& hi) {
    asm("mov.b64 {%0,%1},%2;" : "=f"(lo), "=f"(hi) : "l"(v));
}
__device__ __forceinline__ u64 ffma2(u64 a, u64 b, u64 c) {
    u64 d; asm("fma.rn.f32x2 %0,%1,%2,%3;" : "=l"(d) : "l"(a), "l"(b), "l"(c)); return d;
}
__device__ __forceinline__ u64 fadd2(u64 a, u64 b) {
    u64 d; asm("add.rn.f32x2 %0,%1,%2;" : "=l"(d) : "l"(a), "l"(b)); return d;
}
__device__ __forceinline__ float fex2(float x) { float r; asm("ex2.approx.f32 %0,%1;" : "=f"(r) : "f"(x)); return r; }
__device__ __forceinline__ float frcp(float x) { float r; asm("rcp.approx.f32 %0,%1;" : "=f"(r) : "f"(x)); return r; }
__device__ __forceinline__ float ftanh(float x) { return 1.0f - 2.0f * frcp(fex2(2.8853900817779268f * x) + 1.0f); }
__device__ __forceinline__ float fsigm(float x) { return frcp(1.0f + fex2(-1.4426950408889634f * x)); }
__device__ __forceinline__ u64 tanh2(u64 v) {
    float a, b; unpk2(v, a, b); return pack2(ftanh(a), ftanh(b));
}

// ---------------------------------------------------------------------------
// Phase 1: Dopri5 ODE (EXACT R7 version, best measured ~697us).
// 256 thr = 8 warps, 8 rows = 4 row-pairs (f32x2). Matvec: warp q = k-slice
// [16q,16q+16), all 4 pairs, scalar xs broadcasts. Reduce/RK: warp (p, jh).
// ---------------------------------------------------------------------------
__global__ void __launch_bounds__(256)
ode_kernel(const float* __restrict__ yl, const float* __restrict__ yh,
           const float* __restrict__ W, const float* __restrict__ bias)
{
    extern __shared__ float sm[];
    u64* pbuf = (u64*)(sm + S_ODE * DD);   // [q(8)][p(4)][j(128)] u64 = 32KB
    u64* xs   = pbuf + 4096;               // [p(4)][k(128)] u64 = 4KB
    const int tid = threadIdx.x;
    for (int idx = tid; idx < DD * DD; idx += 256) {
        const int j = idx >> 7, k = idx & 127;
        sm[k * S_ODE + j] = W[idx];
    }
    const int lane = tid & 31, w = tid >> 5;
    const int q = w;
    const int p = w >> 1, jh = w & 1;
    const int j0 = 64 * jh + 2 * lane;
    const int rowA = blockIdx.x * 8 + 2 * p, rowB = rowA + 1;

    const u64 bv0 = dup2(bias[j0]), bv1 = dup2(bias[j0 + 1]);

    float a0 = (j0 < 32) ? yl[rowA * 32 + j0] : yh[rowA * 96 + j0 - 32];
    float b0 = (j0 < 32) ? yl[rowB * 32 + j0] : yh[rowB * 96 + j0 - 32];
    float a1 = (j0 + 1 < 32) ? yl[rowA * 32 + j0 + 1] : yh[rowA * 96 + j0 + 1 - 32];
    float b1 = (j0 + 1 < 32) ? yl[rowB * 32 + j0 + 1] : yh[rowB * 96 + j0 + 1 - 32];
    u64 y0 = pack2(a0, b0), y1 = pack2(a1, b1);
    *(float2*)(g_traj + (size_t)rowA * DD + j0) = make_float2(a0, a1);
    *(float2*)(g_traj + (size_t)rowB * DD + j0) = make_float2(b0, b1);
    *(ulonglong2*)(xs + p * 128 + j0) = make_ulonglong2(y0, y1);
    __syncthreads();

    const u64 dt2 = dup2(1.0f / 95.0f);
    u64 k1[2], k2[2], k3[2], k4[2], k5[2], k6[2], ar[2];

#define ODE_EVAL(KOUT) do { \
    u64 acc[4][4]; \
    _Pragma("unroll") \
    for (int pp = 0; pp < 4; pp++) { acc[pp][0]=0; acc[pp][1]=0; acc[pp][2]=0; acc[pp][3]=0; } \
    _Pragma("unroll") \
    for (int kk = 0; kk < 16; kk++) { \
        const int k = 16 * q + kk; \
        const float4 wv = *(const float4*)(sm + k * S_ODE + 4 * lane); \
        const u64 w0 = dup2(wv.x), w1 = dup2(wv.y), w2 = dup2(wv.z), w3 = dup2(wv.w); \
        const u64 x0 = xs[k], x1 = xs[128 + k], x2 = xs[256 + k], x3 = xs[384 + k]; \
        acc[0][0]=ffma2(x0,w0,acc[0][0]); acc[0][1]=ffma2(x0,w1,acc[0][1]); \
        acc[0][2]=ffma2(x0,w2,acc[0][2]); acc[0][3]=ffma2(x0,w3,acc[0][3]); \
        acc[1][0]=ffma2(x1,w0,acc[1][0]); acc[1][1]=ffma2(x1,w1,acc[1][1]); \
        acc[1][2]=ffma2(x1,w2,acc[1][2]); acc[1][3]=ffma2(x1,w3,acc[1][3]); \
        acc[2][0]=ffma2(x2,w0,acc[2][0]); acc[2][1]=ffma2(x2,w1,acc[2][1]); \
        acc[2][2]=ffma2(x2,w2,acc[2][2]); acc[2][3]=ffma2(x2,w3,acc[2][3]); \
        acc[3][0]=ffma2(x3,w0,acc[3][0]); acc[3][1]=ffma2(x3,w1,acc[3][1]); \
        acc[3][2]=ffma2(x3,w2,acc[3][2]); acc[3][3]=ffma2(x3,w3,acc[3][3]); \
    } \
    _Pragma("unroll") \
    for (int pp = 0; pp < 4; pp++) { \
        u64* base = pbuf + (size_t)(q * 4 + pp) * 128 + 4 * lane; \
        *(ulonglong2*)(base)     = make_ulonglong2(acc[pp][0], acc[pp][1]); \
        *(ulonglong2*)(base + 2) = make_ulonglong2(acc[pp][2], acc[pp][3]); \
    } \
    __syncthreads(); \
    u64 s0 = bv0, s1 = bv1; \
    _Pragma("unroll") \
    for (int qq = 0; qq < 8; qq++) { \
        const ulonglong2 v = *(const ulonglong2*)(pbuf + (size_t)(qq * 4 + p) * 128 + j0); \
        s0 = fadd2(s0, v.x); s1 = fadd2(s1, v.y); \
    } \
    KOUT[0] = tanh2(s0); KOUT[1] = tanh2(s1); \
} while (0)

#define ODE_PUSH() do { \
    *(ulonglong2*)(xs + p * 128 + j0) = make_ulonglong2(ar[0], ar[1]); \
    __syncthreads(); } while (0)

    for (int st = 0; st < NSTEP; st++) {
        ODE_EVAL(k1);
        {
            const u64 c = dup2(0.2f / 95.0f);
            ar[0] = ffma2(c, k1[0], y0); ar[1] = ffma2(c, k1[1], y1);
        }
        ODE_PUSH();

        ODE_EVAL(k2);
#pragma unroll
        for (int m = 0; m < 2; m++) {
            u64 s = ffma2(dup2(0.225f), k2[m], ffma2(dup2(0.075f), k1[m], (u64)0));
            ar[m] = ffma2(dt2, s, m ? y1 : y0);
        }
        ODE_PUSH();

        ODE_EVAL(k3);
#pragma unroll
        for (int m = 0; m < 2; m++) {
            u64 s = ffma2(dup2(0.9777777777777777f), k1[m], (u64)0);
            s = ffma2(dup2(-3.7333333333333334f), k2[m], s);
            s = ffma2(dup2(3.5555555555555554f), k3[m], s);
            ar[m] = ffma2(dt2, s, m ? y1 : y0);
        }
        ODE_PUSH();

        ODE_EVAL(k4);
#pragma unroll
        for (int m = 0; m < 2; m++) {
            u64 s = ffma2(dup2(2.9525906892141633f), k1[m], (u64)0);
            s = ffma2(dup2(-11.595793324188385f), k2[m], s);
            s = ffma2(dup2(9.822892851699436f), k3[m], s);
            s = ffma2(dup2(-0.2908093278463649f), k4[m], s);
            ar[m] = ffma2(dt2, s, m ? y1 : y0);
        }
        ODE_PUSH();

        ODE_EVAL(k5);
#pragma unroll
        for (int m = 0; m < 2; m++) {
            u64 s = ffma2(dup2(2.8462752525252526f), k1[m], (u64)0);
            s = ffma2(dup2(-10.757575757575758f), k2[m], s);
            s = ffma2(dup2(8.906422717743473f), k3[m], s);
            s = ffma2(dup2(0.2784090909090909f), k4[m], s);
            s = ffma2(dup2(-0.2735313036020583f), k5[m], s);
            ar[m] = ffma2(dt2, s, m ? y1 : y0);
        }
        ODE_PUSH();

        ODE_EVAL(k6);
#pragma unroll
        for (int m = 0; m < 2; m++) {
            u64 s = ffma2(dup2(0.09114583333333333f), k1[m], (u64)0);
            s = ffma2(dup2(0.44923629829290207f), k3[m], s);
            s = ffma2(dup2(0.6510416666666666f), k4[m], s);
            s = ffma2(dup2(-0.322376179245283f), k5[m], s);
            s = ffma2(dup2(0.13095238095238096f), k6[m], s);
            if (m == 0) y0 = ffma2(dt2, s, y0); else y1 = ffma2(dt2, s, y1);
        }
        {
            float c0, d0, c1, d1;
            unpk2(y0, c0, d0); unpk2(y1, c1, d1);
            *(float2*)(g_traj + ((size_t)(st + 1) * BATCH + rowA) * DD + j0) = make_float2(c0, c1);
            *(float2*)(g_traj + ((size_t)(st + 1) * BATCH + rowB) * DD + j0) = make_float2(d0, d1);
        }
        *(ulonglong2*)(xs + p * 128 + j0) = make_ulonglong2(y0, y1);
        __syncthreads();
    }
#undef ODE_EVAL
#undef ODE_PUSH
}

// ---------------------------------------------------------------------------
// Phase 2/4: gi = X @ W_ih^T + b_ih (R6 inner loop, grid-stride over 1536
// 64-item blocks on 148 CTAs -> max 11 iters/CTA instead of 12).
// ---------------------------------------------------------------------------
__global__ void __launch_bounds__(512)
gi_kernel(const float* __restrict__ X, const float* __restrict__ Wih,
          const float* __restrict__ bih, float* __restrict__ gi)
{
    extern __shared__ float sm[];
    const int tid = threadIdx.x;
    for (int idx = tid; idx < G3 * DD; idx += 512) {
        const int j = idx >> 7, k = idx & 127;
        sm[k * S_GRU + j] = Wih[idx];
    }
    __syncthreads();

    const int lane = tid & 31, warp = tid >> 5;
    u64 bv[3][2];
#pragma unroll
    for (int g = 0; g < 3; g++) {
        bv[g][0] = pack2(bih[128 * g + 4 * lane], bih[128 * g + 4 * lane + 1]);
        bv[g][1] = pack2(bih[128 * g + 4 * lane + 2], bih[128 * g + 4 * lane + 3]);
    }
    const float* wb = sm + 4 * lane;

#pragma unroll 1
    for (int blk = blockIdx.x; blk < 1536; blk += gridDim.x) {
        const int item = blk * 64 + warp * 4;
        float a[4][4];
#pragma unroll
        for (int i = 0; i < 4; i++) {
            const float4 v = *(const float4*)(X + (size_t)(item + i) * DD + 4 * lane);
            a[i][0] = v.x; a[i][1] = v.y; a[i][2] = v.z; a[i][3] = v.w;
        }
        u64 acc[4][3][2];
#pragma unroll
        for (int i = 0; i < 4; i++)
#pragma unroll
            for (int g = 0; g < 3; g++) { acc[i][g][0] = bv[g][0]; acc[i][g][1] = bv[g][1]; }

#pragma unroll 2
        for (int kb = 0; kb < 32; kb++) {
#pragma unroll
            for (int mk = 0; mk < 4; mk++) {
                const int k = 4 * kb + mk;
                const ulonglong2 w0 = *(const ulonglong2*)(wb + k * S_GRU);
                const ulonglong2 w1 = *(const ulonglong2*)(wb + k * S_GRU + 128);
                const ulonglong2 w2 = *(const ulonglong2*)(wb + k * S_GRU + 256);
#pragma unroll
                for (int i = 0; i < 4; i++) {
                    const u64 xd = dup2(__shfl_sync(0xffffffffu, a[i][mk], kb));
                    acc[i][0][0] = ffma2(xd, w0.x, acc[i][0][0]);
                    acc[i][0][1] = ffma2(xd, w0.y, acc[i][0][1]);
                    acc[i][1][0] = ffma2(xd, w1.x, acc[i][1][0]);
                    acc[i][1][1] = ffma2(xd, w1.y, acc[i][1][1]);
                    acc[i][2][0] = ffma2(xd, w2.x, acc[i][2][0]);
                    acc[i][2][1] = ffma2(xd, w2.y, acc[i][2][1]);
                }
            }
        }
#pragma unroll
        for (int i = 0; i < 4; i++)
#pragma unroll
            for (int g = 0; g < 3; g++)
                *(ulonglong2*)(gi + (size_t)(item + i) * G3 + 128 * g + 4 * lane) =
                    make_ulonglong2(acc[i][g][0], acc[i][g][1]);
    }
}

// ---------------------------------------------------------------------------
// Phase 3/5: GRU scan (EXACT R6 version, best measured 367us). 384 thr.
// ---------------------------------------------------------------------------
__global__ void __launch_bounds__(384)
gru_kernel(const float* __restrict__ gi, const float* __restrict__ Whh,
           const float* __restrict__ bhh, float* __restrict__ otraj,
           float* __restrict__ olast)
{
    extern __shared__ float sm[];
    float* pbuf = sm + DD * S_GRU;   // 6144 floats: [(g*2+ks)*8 + row][128]
    float* xsf  = pbuf + 6144;       // 2048 floats: [row(8)][k] dup pairs
    u64* xsu = (u64*)xsf;
    const int tid = threadIdx.x;
    for (int idx = tid; idx < G3 * DD; idx += 384) {
        const int j = idx >> 7, k = idx & 127;
        sm[k * S_GRU + j] = Whh[idx];
    }
    for (int idx = tid; idx < 2048; idx += 384) xsf[idx] = 0.0f;
    __syncthreads();

    const int lane = tid & 31, wid = tid >> 5;
    const int g = wid >> 2, ks = (wid >> 1) & 1, rh = wid & 1;
    const float* wb = sm + g * 128 + 4 * lane;
    float* pme = pbuf + (size_t)((g * 2 + ks) * 8 + rh * 4) * 128 + 4 * lane;
    const int frow = wid;
    const bool fin = (wid < 8);
    const int grow = blockIdx.x * 8 + frow;

    float br[4], bz[4], bn[4];
    if (fin) {
        const float4 vr = *(const float4*)(bhh + 4 * lane);
        const float4 vz = *(const float4*)(bhh + 128 + 4 * lane);
        const float4 vn = *(const float4*)(bhh + 256 + 4 * lane);
        br[0]=vr.x; br[1]=vr.y; br[2]=vr.z; br[3]=vr.w;
        bz[0]=vz.x; bz[1]=vz.y; bz[2]=vz.z; bz[3]=vz.w;
        bn[0]=vn.x; bn[1]=vn.y; bn[2]=vn.z; bn[3]=vn.w;
    }
    float h[4] = {0.f, 0.f, 0.f, 0.f};

    for (int t = 0; t < TT; t++) {
        float4 gr_, gz_, gn_;
        if (fin) {
            const float* gp = gi + ((size_t)t * BATCH + grow) * G3 + 4 * lane;
            gr_ = *(const float4*)(gp);
            gz_ = *(const float4*)(gp + 128);
            gn_ = *(const float4*)(gp + 256);
        }
        u64 acc[4][2];
#pragma unroll
        for (int r = 0; r < 4; r++) { acc[r][0] = 0; acc[r][1] = 0; }
        const int kbase = 64 * ks;
#pragma unroll 8
        for (int kk = 0; kk < 64; kk += 2) {
            const int k = kbase + kk;
            const ulonglong2 x0 = *(const ulonglong2*)(xsu + (rh * 4 + 0) * 128 + k);
            const ulonglong2 x1 = *(const ulonglong2*)(xsu + (rh * 4 + 1) * 128 + k);
            const ulonglong2 x2 = *(const ulonglong2*)(xsu + (rh * 4 + 2) * 128 + k);
            const ulonglong2 x3 = *(const ulonglong2*)(xsu + (rh * 4 + 3) * 128 + k);
            const ulonglong2 wA = *(const ulonglong2*)(wb + k * S_GRU);
            const ulonglong2 wB = *(const ulonglong2*)(wb + (k + 1) * S_GRU);
            acc[0][0] = ffma2(x0.x, wA.x, acc[0][0]); acc[0][1] = ffma2(x0.x, wA.y, acc[0][1]);
            acc[1][0] = ffma2(x1.x, wA.x, acc[1][0]); acc[1][1] = ffma2(x1.x, wA.y, acc[1][1]);
            acc[2][0] = ffma2(x2.x, wA.x, acc[2][0]); acc[2][1] = ffma2(x2.x, wA.y, acc[2][1]);
            acc[3][0] = ffma2(x3.x, wA.x, acc[3][0]); acc[3][1] = ffma2(x3.x, wA.y, acc[3][1]);
            acc[0][0] = ffma2(x0.y, wB.x, acc[0][0]); acc[0][1] = ffma2(x0.y, wB.y, acc[0][1]);
            acc[1][0] = ffma2(x1.y, wB.x, acc[1][0]); acc[1][1] = ffma2(x1.y, wB.y, acc[1][1]);
            acc[2][0] = ffma2(x2.y, wB.x, acc[2][0]); acc[2][1] = ffma2(x2.y, wB.y, acc[2][1]);
            acc[3][0] = ffma2(x3.y, wB.x, acc[3][0]); acc[3][1] = ffma2(x3.y, wB.y, acc[3][1]);
        }
#pragma unroll
        for (int r = 0; r < 4; r++)
            *(ulonglong2*)(pme + r * 128) = make_ulonglong2(acc[r][0], acc[r][1]);
        __syncthreads();   // A: all partials visible

        if (fin) {
            const float* pb = pbuf + (size_t)frow * 128 + 4 * lane;
            const ulonglong2 pr0 = *(const ulonglong2*)(pb);
            const ulonglong2 pr1 = *(const ulonglong2*)(pb + 8 * 128);
            const ulonglong2 pz0 = *(const ulonglong2*)(pb + 16 * 128);
            const ulonglong2 pz1 = *(const ulonglong2*)(pb + 24 * 128);
            const ulonglong2 pn0 = *(const ulonglong2*)(pb + 32 * 128);
            const ulonglong2 pn1 = *(const ulonglong2*)(pb + 40 * 128);
            float ar[4], az[4], an[4];
            {
                const u64 s0 = fadd2(pr0.x, pr1.x), s1 = fadd2(pr0.y, pr1.y);
                unpk2(s0, ar[0], ar[1]); unpk2(s1, ar[2], ar[3]);
            }
            {
                const u64 s0 = fadd2(pz0.x, pz1.x), s1 = fadd2(pz0.y, pz1.y);
                unpk2(s0, az[0], az[1]); unpk2(s1, az[2], az[3]);
            }
            {
                const u64 s0 = fadd2(pn0.x, pn1.x), s1 = fadd2(pn0.y, pn1.y);
                unpk2(s0, an[0], an[1]); unpk2(s1, an[2], an[3]);
            }
            const float gvr[4] = {gr_.x, gr_.y, gr_.z, gr_.w};
            const float gvz[4] = {gz_.x, gz_.y, gz_.z, gz_.w};
            const float gvn[4] = {gn_.x, gn_.y, gn_.z, gn_.w};
#pragma unroll
            for (int m = 0; m < 4; m++) {
                const float rg = fsigm(gvr[m] + ar[m] + br[m]);
                const float zg = fsigm(gvz[m] + az[m] + bz[m]);
                const float ng = ftanh(gvn[m] + rg * (an[m] + bn[m]));
                h[m] = ng + zg * (h[m] - ng);
            }
            float* xme = xsf + (size_t)(frow * 128 + 4 * lane) * 2;
            *(float4*)(xme)     = make_float4(h[0], h[0], h[1], h[1]);
            *(float4*)(xme + 4) = make_float4(h[2], h[2], h[3], h[3]);
            if (otraj)
                *(float4*)(otraj + ((size_t)t * BATCH + grow) * DD + 4 * lane) =
                    make_float4(h[0], h[1], h[2], h[3]);
        }
        __syncthreads();   // C: new h visible
    }
    if (olast && fin)
        *(float4*)(olast + (size_t)grow * DD + 4 * lane) =
            make_float4(h[0], h[1], h[2], h[3]);
}

// ---------------------------------------------------------------------------
// Phase 6: FC head (unchanged).
// ---------------------------------------------------------------------------
__global__ void __launch_bounds__(256)
fc_kernel(const float* __restrict__ W1, const float* __restrict__ b1,
          const float* __restrict__ W2, const float* __restrict__ b2,
          float* __restrict__ out)
{
    extern __shared__ float sm[];
    float* hs = sm;
    float* hd = sm + 1024;
    float* wt = sm + 1536;
    const int tid = threadIdx.x;
    const int row0 = blockIdx.x * 8;

    for (int idx = tid; idx < 8 * DD; idx += 256) hs[idx] = g_h2[(size_t)row0 * DD + idx];
    for (int idx = tid; idx < 64 * DD; idx += 256) {
        const int j = idx >> 7, k = idx & 127;
        wt[k * 68 + j] = W1[idx];
    }
    __syncthreads();

#pragma unroll
    for (int i = 0; i < 2; i++) {
        const int p = tid + 256 * i, r = p >> 6, j = p & 63;
        float acc = b1[j];
#pragma unroll 8
        for (int k = 0; k < DD; k++) acc = fmaf(hs[r * DD + k], wt[k * 68 + j], acc);
        hd[r * 64 + j] = acc * normcdff(acc);
    }

    for (int c = 0; c < 12; c++) {
        __syncthreads();
        for (int idx = tid; idx < 256 * 64; idx += 256) {
            const int jj = idx >> 6, k = idx & 63;
            wt[k * 260 + jj] = W2[(size_t)(c * 256 + jj) * 64 + k];
        }
        __syncthreads();
        const int j = c * 256 + tid;
        float acc[8];
#pragma unroll
        for (int r = 0; r < 8; r++) acc[r] = b2[j];
#pragma unroll 8
        for (int k = 0; k < 64; k++) {
            const float w = wt[k * 260 + tid];
#pragma unroll
            for (int r = 0; r < 8; r++) acc[r] = fmaf(hd[r * 64 + k], w, acc[r]);
        }
#pragma unroll
        for (int r = 0; r < 8; r++) out[(size_t)(row0 + r) * 3072 + j] = acc[r];
    }
}

// ---------------------------------------------------------------------------
extern "C" void kernel_launch(void* const* d_in, const int* in_sizes, int n_in,
                              void* d_out, int out_size)
{
    (void)in_sizes; (void)n_in; (void)out_size;
    const float* yl    = (const float*)d_in[1];
    const float* yh    = (const float*)d_in[2];
    const float* W_ode = (const float*)d_in[3];
    const float* b_ode = (const float*)d_in[4];
    const float* W_ih0 = (const float*)d_in[5];
    const float* W_hh0 = (const float*)d_in[6];
    const float* b_ih0 = (const float*)d_in[7];
    const float* b_hh0 = (const float*)d_in[8];
    const float* W_ih1 = (const float*)d_in[9];
    const float* W_hh1 = (const float*)d_in[10];
    const float* b_ih1 = (const float*)d_in[11];
    const float* b_hh1 = (const float*)d_in[12];
    const float* W1    = (const float*)d_in[13];
    const float* b1    = (const float*)d_in[14];
    const float* W2    = (const float*)d_in[15];
    const float* b2    = (const float*)d_in[16];
    float* out = (float*)d_out;

    float *traj, *gibuf, *h1, *h2;
    cudaGetSymbolAddress((void**)&traj,  g_traj);
    cudaGetSymbolAddress((void**)&gibuf, g_gi);
    cudaGetSymbolAddress((void**)&h1,    g_h1);
    cudaGetSymbolAddress((void**)&h2,    g_h2);

    const int SM_ODE  = S_ODE * DD * 4 + 32768 + 4096;    // 104,448 B
    const int SM_GI   = S_GRU * DD * 4;                   // 198,656 B
    const int SM_GRU2 = (S_GRU * DD + 6144 + 2048) * 4;   // 231,424 B
    const int SM_FC   = (1536 + 64 * 260) * 4;            //  72,704 B
    cudaFuncSetAttribute(ode_kernel, cudaFuncAttributeMaxDynamicSharedMemorySize, SM_ODE);
    cudaFuncSetAttribute(gi_kernel,  cudaFuncAttributeMaxDynamicSharedMemorySize, SM_GI);
    cudaFuncSetAttribute(gru_kernel, cudaFuncAttributeMaxDynamicSharedMemorySize, SM_GRU2);
    cudaFuncSetAttribute(fc_kernel,  cudaFuncAttributeMaxDynamicSharedMemorySize, SM_FC);

    ode_kernel<<<128, 256, SM_ODE>>>(yl, yh, W_ode, b_ode);
    gi_kernel <<<148, 512, SM_GI>>>(traj, W_ih0, b_ih0, gibuf);
    gru_kernel<<<128, 384, SM_GRU2>>>(gibuf, W_hh0, b_hh0, h1, nullptr);
    gi_kernel <<<148, 512, SM_GI>>>(h1, W_ih1, b_ih1, gibuf);
    gru_kernel<<<128, 384, SM_GRU2>>>(gibuf, W_hh1, b_hh1, nullptr, h2);
    fc_kernel <<<128, 256, SM_FC>>>(W1, b1, W2, b2, out);
}

// round 15
// speedup vs baseline: 1.3178x; 1.0538x over previous
#include <cuda_runtime.h>
#include <math.h>

#define BATCH 1024
#define DD 128
#define G3 384
#define TT 96
#define NSTEP 95
#define S_ODE 132
#define S_GRU 388

typedef unsigned long long u64;

__device__ __align__(256) float g_traj[(size_t)TT * BATCH * DD];
__device__ __align__(256) float g_gi[(size_t)TT * BATCH * G3];
__device__ __align__(256) float g_h1[(size_t)TT * BATCH * DD];
__device__ __align__(256) float g_h2[(size_t)BATCH * DD];

// ---- packed f32x2 + fast transcendental helpers ----
__device__ __forceinline__ u64 pack2(float lo, float hi) {
    u64 r; asm("mov.b64 %0,{%1,%2};" : "=l"(r) : "f"(lo), "f"(hi)); return r;
}
__device__ __forceinline__ u64 dup2(float v) { return pack2(v, v); }
__device__ __forceinline__ void unpk2(u64 v, float& lo, float& hi) {
    asm("mov.b64 {%0,%1},%2;" : "=f"(lo), "=f"(hi) : "l"(v));
}
__device__ __forceinline__ u64 ffma2(u64 a, u64 b, u64 c) {
    u64 d; asm("fma.rn.f32x2 %0,%1,%2,%3;" : "=l"(d) : "l"(a), "l"(b), "l"(c)); return d;
}
__device__ __forceinline__ u64 fadd2(u64 a, u64 b) {
    u64 d; asm("add.rn.f32x2 %0,%1,%2;" : "=l"(d) : "l"(a), "l"(b)); return d;
}
__device__ __forceinline__ float fex2(float x) { float r; asm("ex2.approx.f32 %0,%1;" : "=f"(r) : "f"(x)); return r; }
__device__ __forceinline__ float frcp(float x) { float r; asm("rcp.approx.f32 %0,%1;" : "=f"(r) : "f"(x)); return r; }
__device__ __forceinline__ float ftanh(float x) { return 1.0f - 2.0f * frcp(fex2(2.8853900817779268f * x) + 1.0f); }
__device__ __forceinline__ float fsigm(float x) { return frcp(1.0f + fex2(-1.4426950408889634f * x)); }
__device__ __forceinline__ u64 tanh2(u64 v) {
    float a, b; unpk2(v, a, b); return pack2(ftanh(a), ftanh(b));
}

// ---------------------------------------------------------------------------
// Phase 1: Dopri5 ODE (EXACT R7 version, best measured ~697us).
// ---------------------------------------------------------------------------
__global__ void __launch_bounds__(256)
ode_kernel(const float* __restrict__ yl, const float* __restrict__ yh,
           const float* __restrict__ W, const float* __restrict__ bias)
{
    extern __shared__ float sm[];
    u64* pbuf = (u64*)(sm + S_ODE * DD);
    u64* xs   = pbuf + 4096;
    const int tid = threadIdx.x;
    for (int idx = tid; idx < DD * DD; idx += 256) {
        const int j = idx >> 7, k = idx & 127;
        sm[k * S_ODE + j] = W[idx];
    }
    const int lane = tid & 31, w = tid >> 5;
    const int q = w;
    const int p = w >> 1, jh = w & 1;
    const int j0 = 64 * jh + 2 * lane;
    const int rowA = blockIdx.x * 8 + 2 * p, rowB = rowA + 1;

    const u64 bv0 = dup2(bias[j0]), bv1 = dup2(bias[j0 + 1]);

    float a0 = (j0 < 32) ? yl[rowA * 32 + j0] : yh[rowA * 96 + j0 - 32];
    float b0 = (j0 < 32) ? yl[rowB * 32 + j0] : yh[rowB * 96 + j0 - 32];
    float a1 = (j0 + 1 < 32) ? yl[rowA * 32 + j0 + 1] : yh[rowA * 96 + j0 + 1 - 32];
    float b1 = (j0 + 1 < 32) ? yl[rowB * 32 + j0 + 1] : yh[rowB * 96 + j0 + 1 - 32];
    u64 y0 = pack2(a0, b0), y1 = pack2(a1, b1);
    *(float2*)(g_traj + (size_t)rowA * DD + j0) = make_float2(a0, a1);
    *(float2*)(g_traj + (size_t)rowB * DD + j0) = make_float2(b0, b1);
    *(ulonglong2*)(xs + p * 128 + j0) = make_ulonglong2(y0, y1);
    __syncthreads();

    const u64 dt2 = dup2(1.0f / 95.0f);
    u64 k1[2], k2[2], k3[2], k4[2], k5[2], k6[2], ar[2];

#define ODE_EVAL(KOUT) do { \
    u64 acc[4][4]; \
    _Pragma("unroll") \
    for (int pp = 0; pp < 4; pp++) { acc[pp][0]=0; acc[pp][1]=0; acc[pp][2]=0; acc[pp][3]=0; } \
    _Pragma("unroll") \
    for (int kk = 0; kk < 16; kk++) { \
        const int k = 16 * q + kk; \
        const float4 wv = *(const float4*)(sm + k * S_ODE + 4 * lane); \
        const u64 w0 = dup2(wv.x), w1 = dup2(wv.y), w2 = dup2(wv.z), w3 = dup2(wv.w); \
        const u64 x0 = xs[k], x1 = xs[128 + k], x2 = xs[256 + k], x3 = xs[384 + k]; \
        acc[0][0]=ffma2(x0,w0,acc[0][0]); acc[0][1]=ffma2(x0,w1,acc[0][1]); \
        acc[0][2]=ffma2(x0,w2,acc[0][2]); acc[0][3]=ffma2(x0,w3,acc[0][3]); \
        acc[1][0]=ffma2(x1,w0,acc[1][0]); acc[1][1]=ffma2(x1,w1,acc[1][1]); \
        acc[1][2]=ffma2(x1,w2,acc[1][2]); acc[1][3]=ffma2(x1,w3,acc[1][3]); \
        acc[2][0]=ffma2(x2,w0,acc[2][0]); acc[2][1]=ffma2(x2,w1,acc[2][1]); \
        acc[2][2]=ffma2(x2,w2,acc[2][2]); acc[2][3]=ffma2(x2,w3,acc[2][3]); \
        acc[3][0]=ffma2(x3,w0,acc[3][0]); acc[3][1]=ffma2(x3,w1,acc[3][1]); \
        acc[3][2]=ffma2(x3,w2,acc[3][2]); acc[3][3]=ffma2(x3,w3,acc[3][3]); \
    } \
    _Pragma("unroll") \
    for (int pp = 0; pp < 4; pp++) { \
        u64* base = pbuf + (size_t)(q * 4 + pp) * 128 + 4 * lane; \
        *(ulonglong2*)(base)     = make_ulonglong2(acc[pp][0], acc[pp][1]); \
        *(ulonglong2*)(base + 2) = make_ulonglong2(acc[pp][2], acc[pp][3]); \
    } \
    __syncthreads(); \
    u64 s0 = bv0, s1 = bv1; \
    _Pragma("unroll") \
    for (int qq = 0; qq < 8; qq++) { \
        const ulonglong2 v = *(const ulonglong2*)(pbuf + (size_t)(qq * 4 + p) * 128 + j0); \
        s0 = fadd2(s0, v.x); s1 = fadd2(s1, v.y); \
    } \
    KOUT[0] = tanh2(s0); KOUT[1] = tanh2(s1); \
} while (0)

#define ODE_PUSH() do { \
    *(ulonglong2*)(xs + p * 128 + j0) = make_ulonglong2(ar[0], ar[1]); \
    __syncthreads(); } while (0)

    for (int st = 0; st < NSTEP; st++) {
        ODE_EVAL(k1);
        {
            const u64 c = dup2(0.2f / 95.0f);
            ar[0] = ffma2(c, k1[0], y0); ar[1] = ffma2(c, k1[1], y1);
        }
        ODE_PUSH();

        ODE_EVAL(k2);
#pragma unroll
        for (int m = 0; m < 2; m++) {
            u64 s = ffma2(dup2(0.225f), k2[m], ffma2(dup2(0.075f), k1[m], (u64)0));
            ar[m] = ffma2(dt2, s, m ? y1 : y0);
        }
        ODE_PUSH();

        ODE_EVAL(k3);
#pragma unroll
        for (int m = 0; m < 2; m++) {
            u64 s = ffma2(dup2(0.9777777777777777f), k1[m], (u64)0);
            s = ffma2(dup2(-3.7333333333333334f), k2[m], s);
            s = ffma2(dup2(3.5555555555555554f), k3[m], s);
            ar[m] = ffma2(dt2, s, m ? y1 : y0);
        }
        ODE_PUSH();

        ODE_EVAL(k4);
#pragma unroll
        for (int m = 0; m < 2; m++) {
            u64 s = ffma2(dup2(2.9525906892141633f), k1[m], (u64)0);
            s = ffma2(dup2(-11.595793324188385f), k2[m], s);
            s = ffma2(dup2(9.822892851699436f), k3[m], s);
            s = ffma2(dup2(-0.2908093278463649f), k4[m], s);
            ar[m] = ffma2(dt2, s, m ? y1 : y0);
        }
        ODE_PUSH();

        ODE_EVAL(k5);
#pragma unroll
        for (int m = 0; m < 2; m++) {
            u64 s = ffma2(dup2(2.8462752525252526f), k1[m], (u64)0);
            s = ffma2(dup2(-10.757575757575758f), k2[m], s);
            s = ffma2(dup2(8.906422717743473f), k3[m], s);
            s = ffma2(dup2(0.2784090909090909f), k4[m], s);
            s = ffma2(dup2(-0.2735313036020583f), k5[m], s);
            ar[m] = ffma2(dt2, s, m ? y1 : y0);
        }
        ODE_PUSH();

        ODE_EVAL(k6);
#pragma unroll
        for (int m = 0; m < 2; m++) {
            u64 s = ffma2(dup2(0.09114583333333333f), k1[m], (u64)0);
            s = ffma2(dup2(0.44923629829290207f), k3[m], s);
            s = ffma2(dup2(0.6510416666666666f), k4[m], s);
            s = ffma2(dup2(-0.322376179245283f), k5[m], s);
            s = ffma2(dup2(0.13095238095238096f), k6[m], s);
            if (m == 0) y0 = ffma2(dt2, s, y0); else y1 = ffma2(dt2, s, y1);
        }
        {
            float c0, d0, c1, d1;
            unpk2(y0, c0, d0); unpk2(y1, c1, d1);
            *(float2*)(g_traj + ((size_t)(st + 1) * BATCH + rowA) * DD + j0) = make_float2(c0, c1);
            *(float2*)(g_traj + ((size_t)(st + 1) * BATCH + rowB) * DD + j0) = make_float2(d0, d1);
        }
        *(ulonglong2*)(xs + p * 128 + j0) = make_ulonglong2(y0, y1);
        __syncthreads();
    }
#undef ODE_EVAL
#undef ODE_PUSH
}

// ---------------------------------------------------------------------------
// Phase 2/4: gi (EXACT R14 version: grid-stride 148 CTAs).
// ---------------------------------------------------------------------------
__global__ void __launch_bounds__(512)
gi_kernel(const float* __restrict__ X, const float* __restrict__ Wih,
          const float* __restrict__ bih, float* __restrict__ gi)
{
    extern __shared__ float sm[];
    const int tid = threadIdx.x;
    for (int idx = tid; idx < G3 * DD; idx += 512) {
        const int j = idx >> 7, k = idx & 127;
        sm[k * S_GRU + j] = Wih[idx];
    }
    __syncthreads();

    const int lane = tid & 31, warp = tid >> 5;
    u64 bv[3][2];
#pragma unroll
    for (int g = 0; g < 3; g++) {
        bv[g][0] = pack2(bih[128 * g + 4 * lane], bih[128 * g + 4 * lane + 1]);
        bv[g][1] = pack2(bih[128 * g + 4 * lane + 2], bih[128 * g + 4 * lane + 3]);
    }
    const float* wb = sm + 4 * lane;

#pragma unroll 1
    for (int blk = blockIdx.x; blk < 1536; blk += gridDim.x) {
        const int item = blk * 64 + warp * 4;
        float a[4][4];
#pragma unroll
        for (int i = 0; i < 4; i++) {
            const float4 v = *(const float4*)(X + (size_t)(item + i) * DD + 4 * lane);
            a[i][0] = v.x; a[i][1] = v.y; a[i][2] = v.z; a[i][3] = v.w;
        }
        u64 acc[4][3][2];
#pragma unroll
        for (int i = 0; i < 4; i++)
#pragma unroll
            for (int g = 0; g < 3; g++) { acc[i][g][0] = bv[g][0]; acc[i][g][1] = bv[g][1]; }

#pragma unroll 2
        for (int kb = 0; kb < 32; kb++) {
#pragma unroll
            for (int mk = 0; mk < 4; mk++) {
                const int k = 4 * kb + mk;
                const ulonglong2 w0 = *(const ulonglong2*)(wb + k * S_GRU);
                const ulonglong2 w1 = *(const ulonglong2*)(wb + k * S_GRU + 128);
                const ulonglong2 w2 = *(const ulonglong2*)(wb + k * S_GRU + 256);
#pragma unroll
                for (int i = 0; i < 4; i++) {
                    const u64 xd = dup2(__shfl_sync(0xffffffffu, a[i][mk], kb));
                    acc[i][0][0] = ffma2(xd, w0.x, acc[i][0][0]);
                    acc[i][0][1] = ffma2(xd, w0.y, acc[i][0][1]);
                    acc[i][1][0] = ffma2(xd, w1.x, acc[i][1][0]);
                    acc[i][1][1] = ffma2(xd, w1.y, acc[i][1][1]);
                    acc[i][2][0] = ffma2(xd, w2.x, acc[i][2][0]);
                    acc[i][2][1] = ffma2(xd, w2.y, acc[i][2][1]);
                }
            }
        }
#pragma unroll
        for (int i = 0; i < 4; i++)
#pragma unroll
            for (int g = 0; g < 3; g++)
                *(ulonglong2*)(gi + (size_t)(item + i) * G3 + 128 * g + 4 * lane) =
                    make_ulonglong2(acc[i][g][0], acc[i][g][1]);
    }
}

// ---------------------------------------------------------------------------
// Phase 3/5: GRU scan, pair-lane matvec. 384 thr = 12 warps.
// Matvec: warp (g, ks, ph): gate g, k-half ks, pairs {2ph, 2ph+1}; weights
// from smem float4 (dup'd in reg), xs as packed (rowA,rowB) u64 pairs.
// Partials: pbuf u64 [slot = (g*2+ks)*4 + pair][j]. Finalize: warps 0-7,
// row = frow; pair=frow>>1, half=frow&1; sums ks-halves, extracts its half.
// ---------------------------------------------------------------------------
__global__ void __launch_bounds__(384)
gru_kernel(const float* __restrict__ gi, const float* __restrict__ Whh,
           const float* __restrict__ bhh, float* __restrict__ otraj,
           float* __restrict__ olast)
{
    extern __shared__ float sm[];
    u64* pbuf = (u64*)(sm + DD * S_GRU);   // 24 slots x 128 u64 = 24KB
    u64* xs   = pbuf + 3072;               // [pair(4)][k(128)] u64 = 4KB
    float* xsf = (float*)xs;
    const int tid = threadIdx.x;
    for (int idx = tid; idx < G3 * DD; idx += 384) {
        const int j = idx >> 7, k = idx & 127;
        sm[k * S_GRU + j] = Whh[idx];
    }
    for (int idx = tid; idx < 1024; idx += 384) xsf[idx] = 0.0f;
    __syncthreads();

    const int lane = tid & 31, wid = tid >> 5;
    const int g = wid >> 2, ks = (wid >> 1) & 1, ph = wid & 1;
    const float* wb = sm + g * 128 + 4 * lane;
    u64* pme = pbuf + (size_t)((g * 2 + ks) * 4 + 2 * ph) * 128 + 4 * lane;
    const int frow = wid;
    const bool fin = (wid < 8);
    const int pair_f = frow >> 1, half_f = frow & 1;
    const int grow = blockIdx.x * 8 + frow;

    float br[4], bz[4], bn[4];
    if (fin) {
        const float4 vr = *(const float4*)(bhh + 4 * lane);
        const float4 vz = *(const float4*)(bhh + 128 + 4 * lane);
        const float4 vn = *(const float4*)(bhh + 256 + 4 * lane);
        br[0]=vr.x; br[1]=vr.y; br[2]=vr.z; br[3]=vr.w;
        bz[0]=vz.x; bz[1]=vz.y; bz[2]=vz.z; bz[3]=vz.w;
        bn[0]=vn.x; bn[1]=vn.y; bn[2]=vn.z; bn[3]=vn.w;
    }
    float h[4] = {0.f, 0.f, 0.f, 0.f};

    for (int t = 0; t < TT; t++) {
        float4 gr_, gz_, gn_;
        if (fin) {
            const float* gp = gi + ((size_t)t * BATCH + grow) * G3 + 4 * lane;
            gr_ = *(const float4*)(gp);
            gz_ = *(const float4*)(gp + 128);
            gn_ = *(const float4*)(gp + 256);
        }
        // matvec: pairs {2ph, 2ph+1}, gate g, k-half ks
        u64 acc[2][4];
        acc[0][0]=0; acc[0][1]=0; acc[0][2]=0; acc[0][3]=0;
        acc[1][0]=0; acc[1][1]=0; acc[1][2]=0; acc[1][3]=0;
        const int kbase = 64 * ks;
#pragma unroll 8
        for (int kk = 0; kk < 64; kk += 2) {
            const int k = kbase + kk;
            const float4 wA = *(const float4*)(wb + k * S_GRU);
            const float4 wB = *(const float4*)(wb + (k + 1) * S_GRU);
            const ulonglong2 x0 = *(const ulonglong2*)(xs + (2 * ph + 0) * 128 + k);
            const ulonglong2 x1 = *(const ulonglong2*)(xs + (2 * ph + 1) * 128 + k);
            {
                const u64 w0 = dup2(wA.x), w1 = dup2(wA.y), w2 = dup2(wA.z), w3 = dup2(wA.w);
                acc[0][0]=ffma2(x0.x,w0,acc[0][0]); acc[0][1]=ffma2(x0.x,w1,acc[0][1]);
                acc[0][2]=ffma2(x0.x,w2,acc[0][2]); acc[0][3]=ffma2(x0.x,w3,acc[0][3]);
                acc[1][0]=ffma2(x1.x,w0,acc[1][0]); acc[1][1]=ffma2(x1.x,w1,acc[1][1]);
                acc[1][2]=ffma2(x1.x,w2,acc[1][2]); acc[1][3]=ffma2(x1.x,w3,acc[1][3]);
            }
            {
                const u64 w0 = dup2(wB.x), w1 = dup2(wB.y), w2 = dup2(wB.z), w3 = dup2(wB.w);
                acc[0][0]=ffma2(x0.y,w0,acc[0][0]); acc[0][1]=ffma2(x0.y,w1,acc[0][1]);
                acc[0][2]=ffma2(x0.y,w2,acc[0][2]); acc[0][3]=ffma2(x0.y,w3,acc[0][3]);
                acc[1][0]=ffma2(x1.y,w0,acc[1][0]); acc[1][1]=ffma2(x1.y,w1,acc[1][1]);
                acc[1][2]=ffma2(x1.y,w2,acc[1][2]); acc[1][3]=ffma2(x1.y,w3,acc[1][3]);
            }
        }
        *(ulonglong2*)(pme)       = make_ulonglong2(acc[0][0], acc[0][1]);
        *(ulonglong2*)(pme + 2)   = make_ulonglong2(acc[0][2], acc[0][3]);
        *(ulonglong2*)(pme + 128) = make_ulonglong2(acc[1][0], acc[1][1]);
        *(ulonglong2*)(pme + 130) = make_ulonglong2(acc[1][2], acc[1][3]);
        __syncthreads();   // A: all partials visible

        if (fin) {
            float av[3][4];
#pragma unroll
            for (int g3 = 0; g3 < 3; g3++) {
                const u64* pb = pbuf + (size_t)(8 * g3 + pair_f) * 128 + 4 * lane;
                const ulonglong2 u0 = *(const ulonglong2*)(pb);
                const ulonglong2 u1 = *(const ulonglong2*)(pb + 2);
                const ulonglong2 v0 = *(const ulonglong2*)(pb + 512);
                const ulonglong2 v1 = *(const ulonglong2*)(pb + 514);
                const u64 s0 = fadd2(u0.x, v0.x), s1 = fadd2(u0.y, v0.y);
                const u64 s2 = fadd2(u1.x, v1.x), s3 = fadd2(u1.y, v1.y);
                float lo, hi;
                unpk2(s0, lo, hi); av[g3][0] = half_f ? hi : lo;
                unpk2(s1, lo, hi); av[g3][1] = half_f ? hi : lo;
                unpk2(s2, lo, hi); av[g3][2] = half_f ? hi : lo;
                unpk2(s3, lo, hi); av[g3][3] = half_f ? hi : lo;
            }
            const float gvr[4] = {gr_.x, gr_.y, gr_.z, gr_.w};
            const float gvz[4] = {gz_.x, gz_.y, gz_.z, gz_.w};
            const float gvn[4] = {gn_.x, gn_.y, gn_.z, gn_.w};
#pragma unroll
            for (int m = 0; m < 4; m++) {
                const float rg = fsigm(gvr[m] + av[0][m] + br[m]);
                const float zg = fsigm(gvz[m] + av[1][m] + bz[m]);
                const float ng = ftanh(gvn[m] + rg * (av[2][m] + bn[m]));
                h[m] = ng + zg * (h[m] - ng);
            }
            // write h into pair-packed xs: float index = (pair*128 + j)*2 + half
#pragma unroll
            for (int m = 0; m < 4; m++)
                xsf[(size_t)(pair_f * 128 + 4 * lane + m) * 2 + half_f] = h[m];
            if (otraj)
                *(float4*)(otraj + ((size_t)t * BATCH + grow) * DD + 4 * lane) =
                    make_float4(h[0], h[1], h[2], h[3]);
        }
        __syncthreads();   // C: new h visible
    }
    if (olast && fin)
        *(float4*)(olast + (size_t)grow * DD + 4 * lane) =
            make_float4(h[0], h[1], h[2], h[3]);
}

// ---------------------------------------------------------------------------
// Phase 6: FC head (unchanged).
// ---------------------------------------------------------------------------
__global__ void __launch_bounds__(256)
fc_kernel(const float* __restrict__ W1, const float* __restrict__ b1,
          const float* __restrict__ W2, const float* __restrict__ b2,
          float* __restrict__ out)
{
    extern __shared__ float sm[];
    float* hs = sm;
    float* hd = sm + 1024;
    float* wt = sm + 1536;
    const int tid = threadIdx.x;
    const int row0 = blockIdx.x * 8;

    for (int idx = tid; idx < 8 * DD; idx += 256) hs[idx] = g_h2[(size_t)row0 * DD + idx];
    for (int idx = tid; idx < 64 * DD; idx += 256) {
        const int j = idx >> 7, k = idx & 127;
        wt[k * 68 + j] = W1[idx];
    }
    __syncthreads();

#pragma unroll
    for (int i = 0; i < 2; i++) {
        const int p = tid + 256 * i, r = p >> 6, j = p & 63;
        float acc = b1[j];
#pragma unroll 8
        for (int k = 0; k < DD; k++) acc = fmaf(hs[r * DD + k], wt[k * 68 + j], acc);
        hd[r * 64 + j] = acc * normcdff(acc);
    }

    for (int c = 0; c < 12; c++) {
        __syncthreads();
        for (int idx = tid; idx < 256 * 64; idx += 256) {
            const int jj = idx >> 6, k = idx & 63;
            wt[k * 260 + jj] = W2[(size_t)(c * 256 + jj) * 64 + k];
        }
        __syncthreads();
        const int j = c * 256 + tid;
        float acc[8];
#pragma unroll
        for (int r = 0; r < 8; r++) acc[r] = b2[j];
#pragma unroll 8
        for (int k = 0; k < 64; k++) {
            const float w = wt[k * 260 + tid];
#pragma unroll
            for (int r = 0; r < 8; r++) acc[r] = fmaf(hd[r * 64 + k], w, acc[r]);
        }
#pragma unroll
        for (int r = 0; r < 8; r++) out[(size_t)(row0 + r) * 3072 + j] = acc[r];
    }
}

// ---------------------------------------------------------------------------
extern "C" void kernel_launch(void* const* d_in, const int* in_sizes, int n_in,
                              void* d_out, int out_size)
{
    (void)in_sizes; (void)n_in; (void)out_size;
    const float* yl    = (const float*)d_in[1];
    const float* yh    = (const float*)d_in[2];
    const float* W_ode = (const float*)d_in[3];
    const float* b_ode = (const float*)d_in[4];
    const float* W_ih0 = (const float*)d_in[5];
    const float* W_hh0 = (const float*)d_in[6];
    const float* b_ih0 = (const float*)d_in[7];
    const float* b_hh0 = (const float*)d_in[8];
    const float* W_ih1 = (const float*)d_in[9];
    const float* W_hh1 = (const float*)d_in[10];
    const float* b_ih1 = (const float*)d_in[11];
    const float* b_hh1 = (const float*)d_in[12];
    const float* W1    = (const float*)d_in[13];
    const float* b1    = (const float*)d_in[14];
    const float* W2    = (const float*)d_in[15];
    const float* b2    = (const float*)d_in[16];
    float* out = (float*)d_out;

    float *traj, *gibuf, *h1, *h2;
    cudaGetSymbolAddress((void**)&traj,  g_traj);
    cudaGetSymbolAddress((void**)&gibuf, g_gi);
    cudaGetSymbolAddress((void**)&h1,    g_h1);
    cudaGetSymbolAddress((void**)&h2,    g_h2);

    const int SM_ODE  = S_ODE * DD * 4 + 32768 + 4096;    // 104,448 B
    const int SM_GI   = S_GRU * DD * 4;                   // 198,656 B
    const int SM_GRU2 = S_GRU * DD * 4 + 24576 + 4096;    // 227,328 B
    const int SM_FC   = (1536 + 64 * 260) * 4;            //  72,704 B
    cudaFuncSetAttribute(ode_kernel, cudaFuncAttributeMaxDynamicSharedMemorySize, SM_ODE);
    cudaFuncSetAttribute(gi_kernel,  cudaFuncAttributeMaxDynamicSharedMemorySize, SM_GI);
    cudaFuncSetAttribute(gru_kernel, cudaFuncAttributeMaxDynamicSharedMemorySize, SM_GRU2);
    cudaFuncSetAttribute(fc_kernel,  cudaFuncAttributeMaxDynamicSharedMemorySize, SM_FC);

    ode_kernel<<<128, 256, SM_ODE>>>(yl, yh, W_ode, b_ode);
    gi_kernel <<<148, 512, SM_GI>>>(traj, W_ih0, b_ih0, gibuf);
    gru_kernel<<<128, 384, SM_GRU2>>>(gibuf, W_hh0, b_hh0, h1, nullptr);
    gi_kernel <<<148, 512, SM_GI>>>(h1, W_ih1, b_ih1, gibuf);
    gru_kernel<<<128, 384, SM_GRU2>>>(gibuf, W_hh1, b_hh1, nullptr, h2);
    fc_kernel <<<128, 256, SM_FC>>>(W1, b1, W2, b2, out);
}

// round 16
// speedup vs baseline: 1.3377x; 1.0151x over previous
#include <cuda_runtime.h>
#include <math.h>

#define BATCH 1024
#define DD 128
#define G3 384
#define TT 96
#define NSTEP 95
#define S_GRU 388

typedef unsigned long long u64;

__device__ __align__(256) float g_traj[(size_t)TT * BATCH * DD];
__device__ __align__(256) float g_gi[(size_t)TT * BATCH * G3];
__device__ __align__(256) float g_h1[(size_t)TT * BATCH * DD];
__device__ __align__(256) float g_h2[(size_t)BATCH * DD];

// ---- packed f32x2 + fast transcendental helpers ----
__device__ __forceinline__ u64 pack2(float lo, float hi) {
    u64 r; asm("mov.b64 %0,{%1,%2};" : "=l"(r) : "f"(lo), "f"(hi)); return r;
}
__device__ __forceinline__ u64 dup2(float v) { return pack2(v, v); }
__device__ __forceinline__ void unpk2(u64 v, float& lo, float& hi) {
    asm("mov.b64 {%0,%1},%2;" : "=f"(lo), "=f"(hi) : "l"(v));
}
__device__ __forceinline__ u64 ffma2(u64 a, u64 b, u64 c) {
    u64 d; asm("fma.rn.f32x2 %0,%1,%2,%3;" : "=l"(d) : "l"(a), "l"(b), "l"(c)); return d;
}
__device__ __forceinline__ u64 fadd2(u64 a, u64 b) {
    u64 d; asm("add.rn.f32x2 %0,%1,%2;" : "=l"(d) : "l"(a), "l"(b)); return d;
}
__device__ __forceinline__ float fex2(float x) { float r; asm("ex2.approx.f32 %0,%1;" : "=f"(r) : "f"(x)); return r; }
__device__ __forceinline__ float frcp(float x) { float r; asm("rcp.approx.f32 %0,%1;" : "=f"(r) : "f"(x)); return r; }
__device__ __forceinline__ float ftanh(float x) { return 1.0f - 2.0f * frcp(fex2(2.8853900817779268f * x) + 1.0f); }
__device__ __forceinline__ float fsigm(float x) { return frcp(1.0f + fex2(-1.4426950408889634f * x)); }
__device__ __forceinline__ u64 tanh2(u64 v) {
    float a, b; unpk2(v, a, b); return pack2(ftanh(a), ftanh(b));
}

// ---------------------------------------------------------------------------
// Phase 1: Dopri5 ODE (R7 structure, weights register-resident).
// 256 thr = 8 warps, 8 rows = 4 row-pairs (f32x2). Matvec: warp q = k-slice
// [16q,16q+16), all 4 pairs; weights in 64 regs/thread (w[kk*4+m] =
// W[(4*lane+m)][16q+kk]), xs broadcasts from smem. Reduce/RK: warp (p, jh).
// smem: pbuf 32KB + xs 4KB only.
// ---------------------------------------------------------------------------
__global__ void __launch_bounds__(256)
ode_kernel(const float* __restrict__ yl, const float* __restrict__ yh,
           const float* __restrict__ W, const float* __restrict__ bias)
{
    extern __shared__ float smf[];
    u64* pbuf = (u64*)smf;                 // [q(8)][p(4)][j(128)] u64 = 32KB
    u64* xs   = pbuf + 4096;               // [p(4)][k(128)] u64 = 4KB
    const int tid = threadIdx.x;
    const int lane = tid & 31, w = tid >> 5;
    const int q = w;
    const int p = w >> 1, jh = w & 1;
    const int j0 = 64 * jh + 2 * lane;
    const int rowA = blockIdx.x * 8 + 2 * p, rowB = rowA + 1;

    // register-resident weight slice: wreg[kk*4+m] = W[(4*lane+m)*128 + 16q+kk]
    float wreg[64];
#pragma unroll
    for (int kk = 0; kk < 16; kk++)
#pragma unroll
        for (int m = 0; m < 4; m++)
            wreg[kk * 4 + m] = W[(size_t)(4 * lane + m) * 128 + 16 * q + kk];

    const u64 bv0 = dup2(bias[j0]), bv1 = dup2(bias[j0 + 1]);

    float a0 = (j0 < 32) ? yl[rowA * 32 + j0] : yh[rowA * 96 + j0 - 32];
    float b0 = (j0 < 32) ? yl[rowB * 32 + j0] : yh[rowB * 96 + j0 - 32];
    float a1 = (j0 + 1 < 32) ? yl[rowA * 32 + j0 + 1] : yh[rowA * 96 + j0 + 1 - 32];
    float b1 = (j0 + 1 < 32) ? yl[rowB * 32 + j0 + 1] : yh[rowB * 96 + j0 + 1 - 32];
    u64 y0 = pack2(a0, b0), y1 = pack2(a1, b1);
    *(float2*)(g_traj + (size_t)rowA * DD + j0) = make_float2(a0, a1);
    *(float2*)(g_traj + (size_t)rowB * DD + j0) = make_float2(b0, b1);
    *(ulonglong2*)(xs + p * 128 + j0) = make_ulonglong2(y0, y1);
    __syncthreads();

    const u64 dt2 = dup2(1.0f / 95.0f);
    u64 k1[2], k2[2], k3[2], k4[2], k5[2], k6[2], ar[2];

#define ODE_EVAL(KOUT) do { \
    u64 acc[4][4]; \
    _Pragma("unroll") \
    for (int pp = 0; pp < 4; pp++) { acc[pp][0]=0; acc[pp][1]=0; acc[pp][2]=0; acc[pp][3]=0; } \
    _Pragma("unroll") \
    for (int kk = 0; kk < 16; kk++) { \
        const int k = 16 * q + kk; \
        const u64 w0 = dup2(wreg[kk * 4 + 0]), w1 = dup2(wreg[kk * 4 + 1]); \
        const u64 w2 = dup2(wreg[kk * 4 + 2]), w3 = dup2(wreg[kk * 4 + 3]); \
        const u64 x0 = xs[k], x1 = xs[128 + k], x2 = xs[256 + k], x3 = xs[384 + k]; \
        acc[0][0]=ffma2(x0,w0,acc[0][0]); acc[0][1]=ffma2(x0,w1,acc[0][1]); \
        acc[0][2]=ffma2(x0,w2,acc[0][2]); acc[0][3]=ffma2(x0,w3,acc[0][3]); \
        acc[1][0]=ffma2(x1,w0,acc[1][0]); acc[1][1]=ffma2(x1,w1,acc[1][1]); \
        acc[1][2]=ffma2(x1,w2,acc[1][2]); acc[1][3]=ffma2(x1,w3,acc[1][3]); \
        acc[2][0]=ffma2(x2,w0,acc[2][0]); acc[2][1]=ffma2(x2,w1,acc[2][1]); \
        acc[2][2]=ffma2(x2,w2,acc[2][2]); acc[2][3]=ffma2(x2,w3,acc[2][3]); \
        acc[3][0]=ffma2(x3,w0,acc[3][0]); acc[3][1]=ffma2(x3,w1,acc[3][1]); \
        acc[3][2]=ffma2(x3,w2,acc[3][2]); acc[3][3]=ffma2(x3,w3,acc[3][3]); \
    } \
    _Pragma("unroll") \
    for (int pp = 0; pp < 4; pp++) { \
        u64* base = pbuf + (size_t)(q * 4 + pp) * 128 + 4 * lane; \
        *(ulonglong2*)(base)     = make_ulonglong2(acc[pp][0], acc[pp][1]); \
        *(ulonglong2*)(base + 2) = make_ulonglong2(acc[pp][2], acc[pp][3]); \
    } \
    __syncthreads(); \
    u64 s0 = bv0, s1 = bv1; \
    _Pragma("unroll") \
    for (int qq = 0; qq < 8; qq++) { \
        const ulonglong2 v = *(const ulonglong2*)(pbuf + (size_t)(qq * 4 + p) * 128 + j0); \
        s0 = fadd2(s0, v.x); s1 = fadd2(s1, v.y); \
    } \
    KOUT[0] = tanh2(s0); KOUT[1] = tanh2(s1); \
} while (0)

#define ODE_PUSH() do { \
    *(ulonglong2*)(xs + p * 128 + j0) = make_ulonglong2(ar[0], ar[1]); \
    __syncthreads(); } while (0)

    for (int st = 0; st < NSTEP; st++) {
        ODE_EVAL(k1);
        {
            const u64 c = dup2(0.2f / 95.0f);
            ar[0] = ffma2(c, k1[0], y0); ar[1] = ffma2(c, k1[1], y1);
        }
        ODE_PUSH();

        ODE_EVAL(k2);
#pragma unroll
        for (int m = 0; m < 2; m++) {
            u64 s = ffma2(dup2(0.225f), k2[m], ffma2(dup2(0.075f), k1[m], (u64)0));
            ar[m] = ffma2(dt2, s, m ? y1 : y0);
        }
        ODE_PUSH();

        ODE_EVAL(k3);
#pragma unroll
        for (int m = 0; m < 2; m++) {
            u64 s = ffma2(dup2(0.9777777777777777f), k1[m], (u64)0);
            s = ffma2(dup2(-3.7333333333333334f), k2[m], s);
            s = ffma2(dup2(3.5555555555555554f), k3[m], s);
            ar[m] = ffma2(dt2, s, m ? y1 : y0);
        }
        ODE_PUSH();

        ODE_EVAL(k4);
#pragma unroll
        for (int m = 0; m < 2; m++) {
            u64 s = ffma2(dup2(2.9525906892141633f), k1[m], (u64)0);
            s = ffma2(dup2(-11.595793324188385f), k2[m], s);
            s = ffma2(dup2(9.822892851699436f), k3[m], s);
            s = ffma2(dup2(-0.2908093278463649f), k4[m], s);
            ar[m] = ffma2(dt2, s, m ? y1 : y0);
        }
        ODE_PUSH();

        ODE_EVAL(k5);
#pragma unroll
        for (int m = 0; m < 2; m++) {
            u64 s = ffma2(dup2(2.8462752525252526f), k1[m], (u64)0);
            s = ffma2(dup2(-10.757575757575758f), k2[m], s);
            s = ffma2(dup2(8.906422717743473f), k3[m], s);
            s = ffma2(dup2(0.2784090909090909f), k4[m], s);
            s = ffma2(dup2(-0.2735313036020583f), k5[m], s);
            ar[m] = ffma2(dt2, s, m ? y1 : y0);
        }
        ODE_PUSH();

        ODE_EVAL(k6);
#pragma unroll
        for (int m = 0; m < 2; m++) {
            u64 s = ffma2(dup2(0.09114583333333333f), k1[m], (u64)0);
            s = ffma2(dup2(0.44923629829290207f), k3[m], s);
            s = ffma2(dup2(0.6510416666666666f), k4[m], s);
            s = ffma2(dup2(-0.322376179245283f), k5[m], s);
            s = ffma2(dup2(0.13095238095238096f), k6[m], s);
            if (m == 0) y0 = ffma2(dt2, s, y0); else y1 = ffma2(dt2, s, y1);
        }
        {
            float c0, d0, c1, d1;
            unpk2(y0, c0, d0); unpk2(y1, c1, d1);
            *(float2*)(g_traj + ((size_t)(st + 1) * BATCH + rowA) * DD + j0) = make_float2(c0, c1);
            *(float2*)(g_traj + ((size_t)(st + 1) * BATCH + rowB) * DD + j0) = make_float2(d0, d1);
        }
        *(ulonglong2*)(xs + p * 128 + j0) = make_ulonglong2(y0, y1);
        __syncthreads();
    }
#undef ODE_EVAL
#undef ODE_PUSH
}

// ---------------------------------------------------------------------------
// Phase 2/4: gi (EXACT R14 version: grid-stride 148 CTAs).
// ---------------------------------------------------------------------------
__global__ void __launch_bounds__(512)
gi_kernel(const float* __restrict__ X, const float* __restrict__ Wih,
          const float* __restrict__ bih, float* __restrict__ gi)
{
    extern __shared__ float sm[];
    const int tid = threadIdx.x;
    for (int idx = tid; idx < G3 * DD; idx += 512) {
        const int j = idx >> 7, k = idx & 127;
        sm[k * S_GRU + j] = Wih[idx];
    }
    __syncthreads();

    const int lane = tid & 31, warp = tid >> 5;
    u64 bv[3][2];
#pragma unroll
    for (int g = 0; g < 3; g++) {
        bv[g][0] = pack2(bih[128 * g + 4 * lane], bih[128 * g + 4 * lane + 1]);
        bv[g][1] = pack2(bih[128 * g + 4 * lane + 2], bih[128 * g + 4 * lane + 3]);
    }
    const float* wb = sm + 4 * lane;

#pragma unroll 1
    for (int blk = blockIdx.x; blk < 1536; blk += gridDim.x) {
        const int item = blk * 64 + warp * 4;
        float a[4][4];
#pragma unroll
        for (int i = 0; i < 4; i++) {
            const float4 v = *(const float4*)(X + (size_t)(item + i) * DD + 4 * lane);
            a[i][0] = v.x; a[i][1] = v.y; a[i][2] = v.z; a[i][3] = v.w;
        }
        u64 acc[4][3][2];
#pragma unroll
        for (int i = 0; i < 4; i++)
#pragma unroll
            for (int g = 0; g < 3; g++) { acc[i][g][0] = bv[g][0]; acc[i][g][1] = bv[g][1]; }

#pragma unroll 2
        for (int kb = 0; kb < 32; kb++) {
#pragma unroll
            for (int mk = 0; mk < 4; mk++) {
                const int k = 4 * kb + mk;
                const ulonglong2 w0 = *(const ulonglong2*)(wb + k * S_GRU);
                const ulonglong2 w1 = *(const ulonglong2*)(wb + k * S_GRU + 128);
                const ulonglong2 w2 = *(const ulonglong2*)(wb + k * S_GRU + 256);
#pragma unroll
                for (int i = 0; i < 4; i++) {
                    const u64 xd = dup2(__shfl_sync(0xffffffffu, a[i][mk], kb));
                    acc[i][0][0] = ffma2(xd, w0.x, acc[i][0][0]);
                    acc[i][0][1] = ffma2(xd, w0.y, acc[i][0][1]);
                    acc[i][1][0] = ffma2(xd, w1.x, acc[i][1][0]);
                    acc[i][1][1] = ffma2(xd, w1.y, acc[i][1][1]);
                    acc[i][2][0] = ffma2(xd, w2.x, acc[i][2][0]);
                    acc[i][2][1] = ffma2(xd, w2.y, acc[i][2][1]);
                }
            }
        }
#pragma unroll
        for (int i = 0; i < 4; i++)
#pragma unroll
            for (int g = 0; g < 3; g++)
                *(ulonglong2*)(gi + (size_t)(item + i) * G3 + 128 * g + 4 * lane) =
                    make_ulonglong2(acc[i][g][0], acc[i][g][1]);
    }
}

// ---------------------------------------------------------------------------
// Phase 3/5: GRU scan (EXACT R15 version: pair-lane matvec). 384 thr.
// ---------------------------------------------------------------------------
__global__ void __launch_bounds__(384)
gru_kernel(const float* __restrict__ gi, const float* __restrict__ Whh,
           const float* __restrict__ bhh, float* __restrict__ otraj,
           float* __restrict__ olast)
{
    extern __shared__ float sm[];
    u64* pbuf = (u64*)(sm + DD * S_GRU);   // 24 slots x 128 u64 = 24KB
    u64* xs   = pbuf + 3072;               // [pair(4)][k(128)] u64 = 4KB
    float* xsf = (float*)xs;
    const int tid = threadIdx.x;
    for (int idx = tid; idx < G3 * DD; idx += 384) {
        const int j = idx >> 7, k = idx & 127;
        sm[k * S_GRU + j] = Whh[idx];
    }
    for (int idx = tid; idx < 1024; idx += 384) xsf[idx] = 0.0f;
    __syncthreads();

    const int lane = tid & 31, wid = tid >> 5;
    const int g = wid >> 2, ks = (wid >> 1) & 1, ph = wid & 1;
    const float* wb = sm + g * 128 + 4 * lane;
    u64* pme = pbuf + (size_t)((g * 2 + ks) * 4 + 2 * ph) * 128 + 4 * lane;
    const int frow = wid;
    const bool fin = (wid < 8);
    const int pair_f = frow >> 1, half_f = frow & 1;
    const int grow = blockIdx.x * 8 + frow;

    float br[4], bz[4], bn[4];
    if (fin) {
        const float4 vr = *(const float4*)(bhh + 4 * lane);
        const float4 vz = *(const float4*)(bhh + 128 + 4 * lane);
        const float4 vn = *(const float4*)(bhh + 256 + 4 * lane);
        br[0]=vr.x; br[1]=vr.y; br[2]=vr.z; br[3]=vr.w;
        bz[0]=vz.x; bz[1]=vz.y; bz[2]=vz.z; bz[3]=vz.w;
        bn[0]=vn.x; bn[1]=vn.y; bn[2]=vn.z; bn[3]=vn.w;
    }
    float h[4] = {0.f, 0.f, 0.f, 0.f};

    for (int t = 0; t < TT; t++) {
        float4 gr_, gz_, gn_;
        if (fin) {
            const float* gp = gi + ((size_t)t * BATCH + grow) * G3 + 4 * lane;
            gr_ = *(const float4*)(gp);
            gz_ = *(const float4*)(gp + 128);
            gn_ = *(const float4*)(gp + 256);
        }
        u64 acc[2][4];
        acc[0][0]=0; acc[0][1]=0; acc[0][2]=0; acc[0][3]=0;
        acc[1][0]=0; acc[1][1]=0; acc[1][2]=0; acc[1][3]=0;
        const int kbase = 64 * ks;
#pragma unroll 8
        for (int kk = 0; kk < 64; kk += 2) {
            const int k = kbase + kk;
            const float4 wA = *(const float4*)(wb + k * S_GRU);
            const float4 wB = *(const float4*)(wb + (k + 1) * S_GRU);
            const ulonglong2 x0 = *(const ulonglong2*)(xs + (2 * ph + 0) * 128 + k);
            const ulonglong2 x1 = *(const ulonglong2*)(xs + (2 * ph + 1) * 128 + k);
            {
                const u64 w0 = dup2(wA.x), w1 = dup2(wA.y), w2 = dup2(wA.z), w3 = dup2(wA.w);
                acc[0][0]=ffma2(x0.x,w0,acc[0][0]); acc[0][1]=ffma2(x0.x,w1,acc[0][1]);
                acc[0][2]=ffma2(x0.x,w2,acc[0][2]); acc[0][3]=ffma2(x0.x,w3,acc[0][3]);
                acc[1][0]=ffma2(x1.x,w0,acc[1][0]); acc[1][1]=ffma2(x1.x,w1,acc[1][1]);
                acc[1][2]=ffma2(x1.x,w2,acc[1][2]); acc[1][3]=ffma2(x1.x,w3,acc[1][3]);
            }
            {
                const u64 w0 = dup2(wB.x), w1 = dup2(wB.y), w2 = dup2(wB.z), w3 = dup2(wB.w);
                acc[0][0]=ffma2(x0.y,w0,acc[0][0]); acc[0][1]=ffma2(x0.y,w1,acc[0][1]);
                acc[0][2]=ffma2(x0.y,w2,acc[0][2]); acc[0][3]=ffma2(x0.y,w3,acc[0][3]);
                acc[1][0]=ffma2(x1.y,w0,acc[1][0]); acc[1][1]=ffma2(x1.y,w1,acc[1][1]);
                acc[1][2]=ffma2(x1.y,w2,acc[1][2]); acc[1][3]=ffma2(x1.y,w3,acc[1][3]);
            }
        }
        *(ulonglong2*)(pme)       = make_ulonglong2(acc[0][0], acc[0][1]);
        *(ulonglong2*)(pme + 2)   = make_ulonglong2(acc[0][2], acc[0][3]);
        *(ulonglong2*)(pme + 128) = make_ulonglong2(acc[1][0], acc[1][1]);
        *(ulonglong2*)(pme + 130) = make_ulonglong2(acc[1][2], acc[1][3]);
        __syncthreads();   // A

        if (fin) {
            float av[3][4];
#pragma unroll
            for (int g3 = 0; g3 < 3; g3++) {
                const u64* pb = pbuf + (size_t)(8 * g3 + pair_f) * 128 + 4 * lane;
                const ulonglong2 u0 = *(const ulonglong2*)(pb);
                const ulonglong2 u1 = *(const ulonglong2*)(pb + 2);
                const ulonglong2 v0 = *(const ulonglong2*)(pb + 512);
                const ulonglong2 v1 = *(const ulonglong2*)(pb + 514);
                const u64 s0 = fadd2(u0.x, v0.x), s1 = fadd2(u0.y, v0.y);
                const u64 s2 = fadd2(u1.x, v1.x), s3 = fadd2(u1.y, v1.y);
                float lo, hi;
                unpk2(s0, lo, hi); av[g3][0] = half_f ? hi : lo;
                unpk2(s1, lo, hi); av[g3][1] = half_f ? hi : lo;
                unpk2(s2, lo, hi); av[g3][2] = half_f ? hi : lo;
                unpk2(s3, lo, hi); av[g3][3] = half_f ? hi : lo;
            }
            const float gvr[4] = {gr_.x, gr_.y, gr_.z, gr_.w};
            const float gvz[4] = {gz_.x, gz_.y, gz_.z, gz_.w};
            const float gvn[4] = {gn_.x, gn_.y, gn_.z, gn_.w};
#pragma unroll
            for (int m = 0; m < 4; m++) {
                const float rg = fsigm(gvr[m] + av[0][m] + br[m]);
                const float zg = fsigm(gvz[m] + av[1][m] + bz[m]);
                const float ng = ftanh(gvn[m] + rg * (av[2][m] + bn[m]));
                h[m] = ng + zg * (h[m] - ng);
            }
#pragma unroll
            for (int m = 0; m < 4; m++)
                xsf[(size_t)(pair_f * 128 + 4 * lane + m) * 2 + half_f] = h[m];
            if (otraj)
                *(float4*)(otraj + ((size_t)t * BATCH + grow) * DD + 4 * lane) =
                    make_float4(h[0], h[1], h[2], h[3]);
        }
        __syncthreads();   // C
    }
    if (olast && fin)
        *(float4*)(olast + (size_t)grow * DD + 4 * lane) =
            make_float4(h[0], h[1], h[2], h[3]);
}

// ---------------------------------------------------------------------------
// Phase 6: FC head (unchanged).
// ---------------------------------------------------------------------------
__global__ void __launch_bounds__(256)
fc_kernel(const float* __restrict__ W1, const float* __restrict__ b1,
          const float* __restrict__ W2, const float* __restrict__ b2,
          float* __restrict__ out)
{
    extern __shared__ float sm[];
    float* hs = sm;
    float* hd = sm + 1024;
    float* wt = sm + 1536;
    const int tid = threadIdx.x;
    const int row0 = blockIdx.x * 8;

    for (int idx = tid; idx < 8 * DD; idx += 256) hs[idx] = g_h2[(size_t)row0 * DD + idx];
    for (int idx = tid; idx < 64 * DD; idx += 256) {
        const int j = idx >> 7, k = idx & 127;
        wt[k * 68 + j] = W1[idx];
    }
    __syncthreads();

#pragma unroll
    for (int i = 0; i < 2; i++) {
        const int p = tid + 256 * i, r = p >> 6, j = p & 63;
        float acc = b1[j];
#pragma unroll 8
        for (int k = 0; k < DD; k++) acc = fmaf(hs[r * DD + k], wt[k * 68 + j], acc);
        hd[r * 64 + j] = acc * normcdff(acc);
    }

    for (int c = 0; c < 12; c++) {
        __syncthreads();
        for (int idx = tid; idx < 256 * 64; idx += 256) {
            const int jj = idx >> 6, k = idx & 63;
            wt[k * 260 + jj] = W2[(size_t)(c * 256 + jj) * 64 + k];
        }
        __syncthreads();
        const int j = c * 256 + tid;
        float acc[8];
#pragma unroll
        for (int r = 0; r < 8; r++) acc[r] = b2[j];
#pragma unroll 8
        for (int k = 0; k < 64; k++) {
            const float w = wt[k * 260 + tid];
#pragma unroll
            for (int r = 0; r < 8; r++) acc[r] = fmaf(hd[r * 64 + k], w, acc[r]);
        }
#pragma unroll
        for (int r = 0; r < 8; r++) out[(size_t)(row0 + r) * 3072 + j] = acc[r];
    }
}

// ---------------------------------------------------------------------------
extern "C" void kernel_launch(void* const* d_in, const int* in_sizes, int n_in,
                              void* d_out, int out_size)
{
    (void)in_sizes; (void)n_in; (void)out_size;
    const float* yl    = (const float*)d_in[1];
    const float* yh    = (const float*)d_in[2];
    const float* W_ode = (const float*)d_in[3];
    const float* b_ode = (const float*)d_in[4];
    const float* W_ih0 = (const float*)d_in[5];
    const float* W_hh0 = (const float*)d_in[6];
    const float* b_ih0 = (const float*)d_in[7];
    const float* b_hh0 = (const float*)d_in[8];
    const float* W_ih1 = (const float*)d_in[9];
    const float* W_hh1 = (const float*)d_in[10];
    const float* b_ih1 = (const float*)d_in[11];
    const float* b_hh1 = (const float*)d_in[12];
    const float* W1    = (const float*)d_in[13];
    const float* b1    = (const float*)d_in[14];
    const float* W2    = (const float*)d_in[15];
    const float* b2    = (const float*)d_in[16];
    float* out = (float*)d_out;

    float *traj, *gibuf, *h1, *h2;
    cudaGetSymbolAddress((void**)&traj,  g_traj);
    cudaGetSymbolAddress((void**)&gibuf, g_gi);
    cudaGetSymbolAddress((void**)&h1,    g_h1);
    cudaGetSymbolAddress((void**)&h2,    g_h2);

    const int SM_ODE  = (4096 + 512) * 8;                 //  36,864 B
    const int SM_GI   = S_GRU * DD * 4;                   // 198,656 B
    const int SM_GRU2 = S_GRU * DD * 4 + 24576 + 4096;    // 227,328 B
    const int SM_FC   = (1536 + 64 * 260) * 4;            //  72,704 B
    cudaFuncSetAttribute(ode_kernel, cudaFuncAttributeMaxDynamicSharedMemorySize, SM_ODE);
    cudaFuncSetAttribute(gi_kernel,  cudaFuncAttributeMaxDynamicSharedMemorySize, SM_GI);
    cudaFuncSetAttribute(gru_kernel, cudaFuncAttributeMaxDynamicSharedMemorySize, SM_GRU2);
    cudaFuncSetAttribute(fc_kernel,  cudaFuncAttributeMaxDynamicSharedMemorySize, SM_FC);

    ode_kernel<<<128, 256, SM_ODE>>>(yl, yh, W_ode, b_ode);
    gi_kernel <<<148, 512, SM_GI>>>(traj, W_ih0, b_ih0, gibuf);
    gru_kernel<<<128, 384, SM_GRU2>>>(gibuf, W_hh0, b_hh0, h1, nullptr);
    gi_kernel <<<148, 512, SM_GI>>>(h1, W_ih1, b_ih1, gibuf);
    gru_kernel<<<128, 384, SM_GRU2>>>(gibuf, W_hh1, b_hh1, nullptr, h2);
    fc_kernel <<<128, 256, SM_FC>>>(W1, b1, W2, b2, out);
}